// round 15
// baseline (speedup 1.0000x reference)
#include <cuda_runtime.h>
#include <cuda_bf16.h>
#include <stdint.h>
#include <math.h>

// ---------------- problem constants ----------------
#define BATCH 64
#define HDIM 56
#define WDIM 56
#define CDIM 128
#define NHEAD 4
#define WSZ 7
#define SHIFT 3
#define NTOK 49
#define NWIN 64
#define NWB (BATCH * NWIN)
#define MROWS (NWB * NTOK)   // 200704
#define HID 512

// ---------------- scratch ----------------
__device__ __align__(256) __nv_bfloat16 g_qkv[(size_t)MROWS * 3 * CDIM];
__device__ __align__(256) __nv_bfloat16 g_vlo[(size_t)MROWS * CDIM];
__device__ __align__(256) __nv_bfloat16 g_attn[(size_t)MROWS * CDIM];
__device__ __align__(256) __nv_bfloat16 g_wq[3 * CDIM * CDIM];
__device__ __align__(256) __nv_bfloat16 g_wp[CDIM * CDIM];
__device__ __align__(256) __nv_bfloat16 g_w1[HID * CDIM];
__device__ __align__(256) __nv_bfloat16 g_w2[CDIM * HID];

// ---------------- tensor-core helpers ----------------
__device__ __forceinline__ void ldsm4(uint32_t& r0, uint32_t& r1, uint32_t& r2, uint32_t& r3,
                                      uint32_t addr) {
    asm volatile("ldmatrix.sync.aligned.m8n8.x4.shared.b16 {%0,%1,%2,%3}, [%4];"
                 : "=r"(r0), "=r"(r1), "=r"(r2), "=r"(r3) : "r"(addr));
}
__device__ __forceinline__ void ldsm4t(uint32_t& r0, uint32_t& r1, uint32_t& r2, uint32_t& r3,
                                       uint32_t addr) {
    asm volatile("ldmatrix.sync.aligned.m8n8.x4.trans.shared.b16 {%0,%1,%2,%3}, [%4];"
                 : "=r"(r0), "=r"(r1), "=r"(r2), "=r"(r3) : "r"(addr));
}
__device__ __forceinline__ void mma16816(float* c, const uint32_t* a, uint32_t b0, uint32_t b1) {
    asm volatile("mma.sync.aligned.m16n8k16.row.col.f32.bf16.bf16.f32 "
                 "{%0,%1,%2,%3}, {%4,%5,%6,%7}, {%8,%9}, {%0,%1,%2,%3};"
                 : "+f"(c[0]), "+f"(c[1]), "+f"(c[2]), "+f"(c[3])
                 : "r"(a[0]), "r"(a[1]), "r"(a[2]), "r"(a[3]), "r"(b0), "r"(b1));
}
__device__ __forceinline__ uint32_t pack_bf2(float a, float b) {
    __nv_bfloat162 t = __floats2bfloat162_rn(a, b);
    return *(uint32_t*)&t;
}
#define CP_ASYNC16(dst, src) asm volatile("cp.async.cg.shared.global [%0], [%1], 16;" :: "r"(dst), "l"(src))
#define CP_COMMIT() asm volatile("cp.async.commit_group;")

// padded-tile micro-step (144B stride) — used by qkv_fused
__device__ __forceinline__ void mma_tile(const unsigned char* sa, const unsigned char* sb,
                                         int wm, int wn, int lane, float acc[2][8][4]) {
    const int mat = lane >> 3, l7 = lane & 7;
    #pragma unroll
    for (int ks = 0; ks < 4; ks++) {
        const int kc = ks * 2;
        uint32_t a[2][4];
        #pragma unroll
        for (int tm = 0; tm < 2; tm++) {
            int r = wm * 32 + tm * 16 + (mat & 1) * 8 + l7;
            int c = kc + (mat >> 1);
            ldsm4(a[tm][0], a[tm][1], a[tm][2], a[tm][3],
                  (uint32_t)__cvta_generic_to_shared(sa + r * 144 + c * 16));
        }
        uint32_t b[4][4];
        #pragma unroll
        for (int tn2 = 0; tn2 < 4; tn2++) {
            int n = wn * 64 + tn2 * 16 + (mat >> 1) * 8 + l7;
            int c = kc + (mat & 1);
            ldsm4(b[tn2][0], b[tn2][1], b[tn2][2], b[tn2][3],
                  (uint32_t)__cvta_generic_to_shared(sb + n * 144 + c * 16));
        }
        #pragma unroll
        for (int tm = 0; tm < 2; tm++)
            #pragma unroll
            for (int tn = 0; tn < 8; tn++)
                mma16816(acc[tm][tn], a[tm], b[tn >> 1][(tn & 1) * 2], b[tn >> 1][(tn & 1) * 2 + 1]);
    }
}

// swizzled-tile micro-step (128B stride, chunk ^= row&7) — used by mlp_fused
__device__ __forceinline__ void mma_tile_sw(const unsigned char* sa, const unsigned char* sb,
                                            int wm, int wn, int lane, float acc[2][8][4]) {
    const int mat = lane >> 3, l7 = lane & 7;
    #pragma unroll
    for (int ks = 0; ks < 4; ks++) {
        const int kc = ks * 2;
        uint32_t a[2][4];
        #pragma unroll
        for (int tm = 0; tm < 2; tm++) {
            int r = wm * 32 + tm * 16 + (mat & 1) * 8 + l7;
            int c = kc + (mat >> 1);
            ldsm4(a[tm][0], a[tm][1], a[tm][2], a[tm][3],
                  (uint32_t)__cvta_generic_to_shared(sa + r * 128 + ((c ^ (r & 7)) * 16)));
        }
        uint32_t b[4][4];
        #pragma unroll
        for (int tn2 = 0; tn2 < 4; tn2++) {
            int n = wn * 64 + tn2 * 16 + (mat >> 1) * 8 + l7;
            int c = kc + (mat & 1);
            ldsm4(b[tn2][0], b[tn2][1], b[tn2][2], b[tn2][3],
                  (uint32_t)__cvta_generic_to_shared(sb + n * 128 + ((c ^ (n & 7)) * 16)));
        }
        #pragma unroll
        for (int tm = 0; tm < 2; tm++)
            #pragma unroll
            for (int tn = 0; tn < 8; tn++)
                mma16816(acc[tm][tn], a[tm], b[tn >> 1][(tn & 1) * 2], b[tn >> 1][(tn & 1) * 2 + 1]);
    }
}

// ---------------- fp32 -> bf16 all four weights, one launch ----------------
__global__ void f2bf_all(const float* __restrict__ wq, const float* __restrict__ wp,
                         const float* __restrict__ w1, const float* __restrict__ w2,
                         __nv_bfloat16* oq, __nv_bfloat16* op,
                         __nv_bfloat16* o1, __nv_bfloat16* o2) {
    int i = blockIdx.x * 256 + threadIdx.x;   // float4 index; total 49152
    const float* src; __nv_bfloat16* dst; int off;
    if (i < 12288)      { src = wq; dst = oq; off = i; }
    else if (i < 16384) { src = wp; dst = op; off = i - 12288; }
    else if (i < 32768) { src = w1; dst = o1; off = i - 16384; }
    else                { src = w2; dst = o2; off = i - 32768; }
    float4 v = ((const float4*)src)[off];
    __nv_bfloat162* o = ((__nv_bfloat162*)dst) + off * 2;
    o[0] = __floats2bfloat162_rn(v.x, v.y);
    o[1] = __floats2bfloat162_rn(v.z, v.w);
}

// ---------------- fused LN1(+shift/window gather) + QKV GEMM ----------------
// smem: A0 @0, A1 @18432, Bbuf0 @36864, Bbuf1 @55296. total 73728.
__global__ void __launch_bounds__(256, 2)
qkv_fused(const float* __restrict__ x, const float* __restrict__ g1, const float* __restrict__ b1,
          const __nv_bfloat16* __restrict__ W, const float* __restrict__ bias,
          __nv_bfloat16* __restrict__ out, __nv_bfloat16* __restrict__ vlo) {
    extern __shared__ unsigned char smem[];
    const int tid = threadIdx.x;
    const int bR = blockIdx.x;
    const int warp = tid >> 5, lane = tid & 31;
    const int wm = warp & 3, wn = warp >> 2;
    const int ldrow = tid >> 3, ldpos = tid & 7;

    auto loadB = [&](int buf, int nt, int kt) {
        unsigned char* sb = smem + 36864 + buf * 18432;
        #pragma unroll
        for (int it = 0; it < 4; it++) {
            int row = ldrow + it * 32;
            uint32_t d = (uint32_t)__cvta_generic_to_shared(sb + row * 144 + ldpos * 16);
            CP_ASYNC16(d, W + (size_t)(nt * 128 + row) * 128 + kt * 64 + ldpos * 8);
        }
        CP_COMMIT();
    };

    loadB(0, 0, 0);
    loadB(1, 0, 1);

    // LN1 + gather into A tiles (warp w -> rows w*16..w*16+15)
    {
        float4 gv = ((const float4*)g1)[lane & 31];
        float4 bv = ((const float4*)b1)[lane & 31];
        unsigned char* At = smem + ((lane & 16) ? 18432 : 0);
        int off = (lane & 15) * 8;
        #pragma unroll 2
        for (int t = 0; t < 16; t++) {
            int row = warp * 16 + t;
            int r = bR * 128 + row;
            int widx = r / NTOK, n = r - widx * NTOK;
            int b = widx >> 6, wi = widx & 63;
            int wh = wi >> 3, ww = wi & 7;
            int i = n / 7, j = n - i * 7;
            int sh = wh * 7 + i + SHIFT; if (sh >= HDIM) sh -= HDIM;
            int sw = ww * 7 + j + SHIFT; if (sw >= WDIM) sw -= WDIM;
            long srow = (long)b * (HDIM * WDIM) + sh * WDIM + sw;
            float4 v = ((const float4*)(x + srow * (long)CDIM))[lane];
            float s = v.x + v.y + v.z + v.w;
            float sq = v.x * v.x + v.y * v.y + v.z * v.z + v.w * v.w;
            #pragma unroll
            for (int o = 16; o; o >>= 1) {
                s  += __shfl_xor_sync(0xFFFFFFFFu, s, o);
                sq += __shfl_xor_sync(0xFFFFFFFFu, sq, o);
            }
            float mu = s * (1.0f / 128.0f);
            float var = sq * (1.0f / 128.0f) - mu * mu;
            float inv = rsqrtf(var + 1e-5f);
            float r0 = (v.x - mu) * inv * gv.x + bv.x;
            float r1 = (v.y - mu) * inv * gv.y + bv.y;
            float r2 = (v.z - mu) * inv * gv.z + bv.z;
            float r3 = (v.w - mu) * inv * gv.w + bv.w;
            *(uint32_t*)(At + row * 144 + off)     = pack_bf2(r0, r1);
            *(uint32_t*)(At + row * 144 + off + 4) = pack_bf2(r2, r3);
        }
    }

    const int gr = lane >> 2, gc = (lane & 3) * 2;
    for (int nt = 0; nt < 3; nt++) {
        float acc[2][8][4];
        #pragma unroll
        for (int i = 0; i < 2; i++)
            #pragma unroll
            for (int j = 0; j < 8; j++)
                #pragma unroll
                for (int q = 0; q < 4; q++) acc[i][j][q] = 0.0f;
        #pragma unroll
        for (int kt = 0; kt < 2; kt++) {
            int idx = nt * 2 + kt;
            if (idx < 5) asm volatile("cp.async.wait_group 1;");
            else         asm volatile("cp.async.wait_group 0;");
            __syncthreads();
            mma_tile(smem + kt * 18432, smem + 36864 + (idx & 1) * 18432, wm, wn, lane, acc);
            __syncthreads();
            if (idx + 2 < 6) loadB(idx & 1, (idx + 2) >> 1, (idx + 2) & 1);
        }
        // epilogue: bias + bf16 store (nt==2 also writes V residual plane)
        #pragma unroll
        for (int tm = 0; tm < 2; tm++) {
            #pragma unroll
            for (int tn = 0; tn < 8; tn++) {
                int col = nt * 128 + wn * 64 + tn * 8 + gc;
                float bs0 = bias[col], bs1 = bias[col + 1];
                int row0 = bR * 128 + wm * 32 + tm * 16 + gr;
                float v0 = acc[tm][tn][0] + bs0, v1 = acc[tm][tn][1] + bs1;
                float v2 = acc[tm][tn][2] + bs0, v3 = acc[tm][tn][3] + bs1;
                uint32_t u0 = pack_bf2(v0, v1), u1 = pack_bf2(v2, v3);
                *(uint32_t*)(out + (size_t)row0 * 384 + col) = u0;
                *(uint32_t*)(out + (size_t)(row0 + 8) * 384 + col) = u1;
                if (nt == 2) {
                    int lc = col - 256;
                    float h0 = __uint_as_float(u0 << 16), h1 = __uint_as_float(u0 & 0xFFFF0000u);
                    float h2 = __uint_as_float(u1 << 16), h3 = __uint_as_float(u1 & 0xFFFF0000u);
                    *(uint32_t*)(vlo + (size_t)row0 * CDIM + lc) = pack_bf2(v0 - h0, v1 - h1);
                    *(uint32_t*)(vlo + (size_t)(row0 + 8) * CDIM + lc) = pack_bf2(v2 - h2, v3 - h3);
                }
            }
        }
    }
}

// ---------------- fused second half, 64-row CTA x 128 threads, 2 CTAs/SM ----------------
// proj + resid + LN2 + fc1 + GELU + fc2 + resid. Swizzled tiles (128B stride),
// 3-buffer W ring -> ONE sync per 64-K step; resid prefetched into x1 stash.
// smem: A/xn2 sub0 @0, sub1 @8192; W ring @16384 (3x16384); h @65536 (2x8192);
//       red overlaid @65536 (proj epilogue only); x1 f32[64][132] @81920 (33792);
//       rowmap @115712. total 115968.
#define MG_W0 16384
#define MG_H0 65536
#define MG_RED 65536
#define MG_X1 81920
#define MG_ROWMAP 115712
#define MLP_SMEM 115968

__global__ void __launch_bounds__(128, 2)
mlp_fused(const __nv_bfloat16* __restrict__ A, const float* __restrict__ resid,
          const __nv_bfloat16* __restrict__ Wp, const float* __restrict__ bp,
          const float* __restrict__ g2, const float* __restrict__ b2,
          const __nv_bfloat16* __restrict__ W1, const float* __restrict__ b1,
          const __nv_bfloat16* __restrict__ W2, const float* __restrict__ b2b,
          float* __restrict__ out) {
    extern __shared__ unsigned char smem[];
    int* rowmap = (int*)(smem + MG_ROWMAP);
    float2* red = (float2*)(smem + MG_RED);
    float* x1s = (float*)(smem + MG_X1);       // stride 132 floats (528B, 16B aligned)
    const int tid = threadIdx.x;
    const int bR = blockIdx.x;
    const int warp = tid >> 5, lane = tid & 31;
    const int wm = warp & 1, wn = warp >> 1;   // 2x2 warp grid, warp tile 32x64
    const int ldrow = tid >> 3, ldpos = tid & 7;
    const int gr = lane >> 2, gc = (lane & 3) * 2;

    if (tid < 64) {
        int r = bR * 64 + tid;
        int b = r / (HDIM * WDIM);
        int l = r - b * (HDIM * WDIM);
        int h = l / WDIM, w = l - h * WDIM;
        int sh = h - SHIFT; if (sh < 0) sh += HDIM;
        int sw = w - SHIFT; if (sw < 0) sw += WDIM;
        int wh = sh / 7, i = sh - wh * 7;
        int ww = sw / 7, j = sw - ww * 7;
        rowmap[tid] = ((b * 64 + wh * 8 + ww) * 49 + i * 7 + j);
    }
    __syncthreads();

    // A prefetch (gathered, swizzled) + resid tile prefetch, one group
    #pragma unroll
    for (int kt = 0; kt < 2; kt++)
        #pragma unroll
        for (int it = 0; it < 4; it++) {
            int row = ldrow + it * 16;
            uint32_t d = (uint32_t)__cvta_generic_to_shared(
                smem + kt * 8192 + row * 128 + ((ldpos ^ (row & 7)) * 16));
            CP_ASYNC16(d, A + (size_t)rowmap[row] * CDIM + kt * 64 + ldpos * 8);
        }
    #pragma unroll
    for (int i = 0; i < 16; i++) {
        int idx = tid + i * 128;               // 2048 16B chunks: 64 rows x 32 chunks
        int row = idx >> 5, c = idx & 31;
        uint32_t d = (uint32_t)__cvta_generic_to_shared(smem + MG_X1 + row * 528 + c * 16);
        CP_ASYNC16(d, resid + ((size_t)(bR * 64 + row)) * CDIM + c * 4);
    }
    CP_COMMIT();

    // weight tile stream into 3-buffer ring: s=0,1 proj; per nt: 2x W1, 2x W2
    auto loadW = [&](int s) {
        const __nv_bfloat16* base; int ld;
        if (s < 2) { base = Wp + s * 64; ld = 128; }
        else {
            int t = s - 2, nt = t >> 2, q = t & 3;
            if (q < 2) { base = W1 + (size_t)(nt * 128) * 128 + q * 64; ld = 128; }
            else       { base = W2 + nt * 128 + (q - 2) * 64; ld = 512; }
        }
        unsigned char* sb = smem + MG_W0 + (s % 3) * 16384;
        #pragma unroll
        for (int it = 0; it < 8; it++) {
            int row = ldrow + it * 16;
            uint32_t d = (uint32_t)__cvta_generic_to_shared(
                sb + row * 128 + ((ldpos ^ (row & 7)) * 16));
            CP_ASYNC16(d, base + (size_t)row * ld + ldpos * 8);
        }
        CP_COMMIT();
    };
    loadW(0); loadW(1);

    // one-sync step: wait(s) -> sync -> issue load(s+2) -> mma(s)
    auto stepHead = [&](int s) {
        if (s < 17) asm volatile("cp.async.wait_group 1;");
        else        asm volatile("cp.async.wait_group 0;");
        __syncthreads();
        if (s + 2 < 18) loadW(s + 2);
    };

    float acc2[2][8][4];
    #pragma unroll
    for (int i = 0; i < 2; i++)
        #pragma unroll
        for (int j = 0; j < 8; j++)
            #pragma unroll
            for (int q = 0; q < 4; q++) acc2[i][j][q] = 0.0f;

    // ---- proj GEMM (steps 0,1) ----
    {
        float acc1[2][8][4];
        #pragma unroll
        for (int i = 0; i < 2; i++)
            #pragma unroll
            for (int j = 0; j < 8; j++)
                #pragma unroll
                for (int q = 0; q < 4; q++) acc1[i][j][q] = 0.0f;
        #pragma unroll
        for (int kt = 0; kt < 2; kt++) {
            int s = kt;
            stepHead(s);
            mma_tile_sw(smem + kt * 8192, smem + MG_W0 + (s % 3) * 16384, wm, wn, lane, acc1);
        }
        // epilogue: + bias + resid(smem) -> x1 (same slots); row stats; LN2 -> xn2 (A tiles)
        float psum[2][2], psq[2][2];
        #pragma unroll
        for (int tm = 0; tm < 2; tm++)
            #pragma unroll
            for (int sl = 0; sl < 2; sl++) { psum[tm][sl] = 0.0f; psq[tm][sl] = 0.0f; }
        #pragma unroll
        for (int tm = 0; tm < 2; tm++) {
            #pragma unroll
            for (int tn = 0; tn < 8; tn++) {
                int col = wn * 64 + tn * 8 + gc;
                float bs0 = bp[col], bs1 = bp[col + 1];
                int lrow0 = wm * 32 + tm * 16 + gr;
                float2 r0 = *(const float2*)(x1s + lrow0 * 132 + col);
                float2 r1 = *(const float2*)(x1s + (lrow0 + 8) * 132 + col);
                float v0 = acc1[tm][tn][0] + bs0 + r0.x;
                float v1 = acc1[tm][tn][1] + bs1 + r0.y;
                float v2 = acc1[tm][tn][2] + bs0 + r1.x;
                float v3 = acc1[tm][tn][3] + bs1 + r1.y;
                acc1[tm][tn][0] = v0; acc1[tm][tn][1] = v1;
                acc1[tm][tn][2] = v2; acc1[tm][tn][3] = v3;
                *(float2*)(x1s + lrow0 * 132 + col) = make_float2(v0, v1);
                *(float2*)(x1s + (lrow0 + 8) * 132 + col) = make_float2(v2, v3);
                psum[tm][0] += v0 + v1;  psq[tm][0] += v0 * v0 + v1 * v1;
                psum[tm][1] += v2 + v3;  psq[tm][1] += v2 * v2 + v3 * v3;
            }
        }
        #pragma unroll
        for (int tm = 0; tm < 2; tm++)
            #pragma unroll
            for (int sl = 0; sl < 2; sl++) {
                float s = psum[tm][sl], q = psq[tm][sl];
                s += __shfl_xor_sync(0xFFFFFFFFu, s, 1); q += __shfl_xor_sync(0xFFFFFFFFu, q, 1);
                s += __shfl_xor_sync(0xFFFFFFFFu, s, 2); q += __shfl_xor_sync(0xFFFFFFFFu, q, 2);
                if ((lane & 3) == 0) red[wn * 64 + wm * 32 + tm * 16 + sl * 8 + gr] = make_float2(s, q);
            }
        __syncthreads();    // red ready; also: all warps done reading A tiles (mma step 1)
        #pragma unroll
        for (int tm = 0; tm < 2; tm++) {
            #pragma unroll
            for (int sl = 0; sl < 2; sl++) {
                int lrow = wm * 32 + tm * 16 + sl * 8 + gr;
                float2 t0 = red[lrow], t1 = red[64 + lrow];
                float mu = (t0.x + t1.x) * (1.0f / 128.0f);
                float var = (t0.y + t1.y) * (1.0f / 128.0f) - mu * mu;
                float inv = rsqrtf(var + 1e-5f);
                #pragma unroll
                for (int tn = 0; tn < 8; tn++) {
                    int col = wn * 64 + tn * 8 + gc;
                    float v0 = acc1[tm][tn][sl * 2 + 0], v1 = acc1[tm][tn][sl * 2 + 1];
                    float n0 = (v0 - mu) * inv * g2[col] + b2[col];
                    float n1 = (v1 - mu) * inv * g2[col + 1] + b2[col + 1];
                    // xn2 -> A tiles (swizzled layout)
                    int ch = (col & 63) >> 3;
                    *(uint32_t*)(smem + (col >> 6) * 8192 + lrow * 128
                                 + ((ch ^ (lrow & 7)) * 16) + (col & 7) * 2) = pack_bf2(n0, n1);
                }
            }
        }
        // no extra sync: step 2's head sync orders xn2 writes before reads
    }

    // ---- MLP: interleaved fc1(nt) -> h tile -> fc2 partial ----
    const float is2 = 0.70710678118654752f;
    for (int nt = 0; nt < 4; nt++) {
        float acc1[2][8][4];
        #pragma unroll
        for (int i = 0; i < 2; i++)
            #pragma unroll
            for (int j = 0; j < 8; j++)
                #pragma unroll
                for (int q = 0; q < 4; q++) acc1[i][j][q] = 0.0f;
        #pragma unroll
        for (int kt = 0; kt < 2; kt++) {
            int s = 2 + nt * 4 + kt;
            stepHead(s);
            mma_tile_sw(smem + kt * 8192, smem + MG_W0 + (s % 3) * 16384, wm, wn, lane, acc1);
        }
        // h epilogue: gelu(acc1 + b1) -> h tiles (swizzled)
        #pragma unroll
        for (int tm = 0; tm < 2; tm++) {
            #pragma unroll
            for (int tn = 0; tn < 8; tn++) {
                int col = wn * 64 + tn * 8 + gc;          // local 0..127
                int colg = nt * 128 + col;
                float bs0 = b1[colg], bs1 = b1[colg + 1];
                int lrow0 = wm * 32 + tm * 16 + gr;
                float v0 = acc1[tm][tn][0] + bs0, v1 = acc1[tm][tn][1] + bs1;
                float v2 = acc1[tm][tn][2] + bs0, v3 = acc1[tm][tn][3] + bs1;
                v0 = 0.5f * v0 * (1.0f + erff(v0 * is2));
                v1 = 0.5f * v1 * (1.0f + erff(v1 * is2));
                v2 = 0.5f * v2 * (1.0f + erff(v2 * is2));
                v3 = 0.5f * v3 * (1.0f + erff(v3 * is2));
                int ch = (col & 63) >> 3;
                int base = MG_H0 + (col >> 6) * 8192 + (col & 7) * 2;
                *(uint32_t*)(smem + base + lrow0 * 128 + ((ch ^ (lrow0 & 7)) * 16)) = pack_bf2(v0, v1);
                int lr1 = lrow0 + 8;
                *(uint32_t*)(smem + base + lr1 * 128 + ((ch ^ (lr1 & 7)) * 16)) = pack_bf2(v2, v3);
            }
        }
        // fc2 partial: next steps' head syncs order h writes before reads
        #pragma unroll
        for (int q = 0; q < 2; q++) {
            int s = 4 + nt * 4 + q;
            stepHead(s);
            mma_tile_sw(smem + MG_H0 + q * 8192, smem + MG_W0 + (s % 3) * 16384, wm, wn, lane, acc2);
        }
    }

    // ---- final epilogue: out = acc2 + b2b + x1 (all thread-local x1 slots) ----
    #pragma unroll
    for (int tm = 0; tm < 2; tm++) {
        #pragma unroll
        for (int tn = 0; tn < 8; tn++) {
            int col = wn * 64 + tn * 8 + gc;
            float bs0 = b2b[col], bs1 = b2b[col + 1];
            int lrow0 = wm * 32 + tm * 16 + gr;
            size_t grow0 = (size_t)(bR * 64 + lrow0);
            float2 x0 = *(const float2*)(x1s + lrow0 * 132 + col);
            float2 x1v = *(const float2*)(x1s + (lrow0 + 8) * 132 + col);
            float v0 = acc2[tm][tn][0] + bs0, v1 = acc2[tm][tn][1] + bs1;
            float v2 = acc2[tm][tn][2] + bs0, v3 = acc2[tm][tn][3] + bs1;
            *(float2*)(out + grow0 * CDIM + col)       = make_float2(v0 + x0.x, v1 + x0.y);
            *(float2*)(out + (grow0 + 8) * CDIM + col) = make_float2(v2 + x1v.x, v3 + x1v.y);
        }
    }
}

// ---------------- tensor-core window attention, split-precision P@V ----------------
__global__ void __launch_bounds__(256)
attn_kernel(const __nv_bfloat16* __restrict__ qkv, const __nv_bfloat16* __restrict__ vlo,
            const float* __restrict__ rpb, __nv_bfloat16* __restrict__ outw) {
    extern __shared__ unsigned char sm[];
    const int widx = blockIdx.x;
    const int tid = threadIdx.x;

    #pragma unroll
    for (int it = 0; it < 12; it++) {
        int idx = it * 256 + tid;
        int c4 = idx & 3, row = (idx >> 2) & 63, h = (idx >> 8) & 3, t = idx >> 10;
        uint4 v = make_uint4(0, 0, 0, 0);
        if (row < 49)
            v = *(const uint4*)(qkv + (size_t)widx * 18816 + row * 384 + t * 128 + h * 32 + c4 * 8);
        *(uint4*)(sm + h * 15360 + t * 5120 + row * 80 + c4 * 16) = v;
    }
    #pragma unroll
    for (int it = 0; it < 4; it++) {
        int idx = it * 256 + tid;
        int c4 = idx & 3, row = (idx >> 2) & 63, h = idx >> 8;
        uint4 v = make_uint4(0, 0, 0, 0);
        if (row < 49)
            v = *(const uint4*)(vlo + ((size_t)widx * 49 + row) * 128 + h * 32 + c4 * 8);
        *(uint4*)(sm + 61440 + h * 5120 + row * 80 + c4 * 16) = v;
    }
    float* rp = (float*)(sm + 81920);
    for (int p = tid; p < 676; p += 256) rp[p] = rpb[(p % 169) * 4 + (p / 169)];
    int* regs = (int*)(sm + 84624);
    signed char* i2t = (signed char*)(sm + 84880);
    signed char* j2t = (signed char*)(sm + 84944);
    if (tid < 64) { i2t[tid] = tid / 7; j2t[tid] = tid % 7; }
    if (tid < 49) {
        int wi = widx & 63;
        int wh = wi >> 3, ww = wi & 7;
        int i = tid / 7, j = tid - i * 7;
        int grr = wh * 7 + i, gcc = ww * 7 + j;
        int rr = grr < 49 ? 0 : (grr < 53 ? 1 : 2);
        int rc = gcc < 49 ? 0 : (gcc < 53 ? 1 : 2);
        regs[tid] = rr * 3 + rc;
    }
    __syncthreads();

    const int warp = tid >> 5, lane = tid & 31;
    const int h = warp >> 1, half = warp & 1;
    const int mat = lane >> 3, l7 = lane & 7, gr = lane >> 2, gc = (lane & 3) * 2;
    const unsigned char* Q = sm + h * 15360;
    const unsigned char* Kp = Q + 5120;
    const unsigned char* Vp = Q + 10240;
    const unsigned char* Vl = sm + 61440 + h * 5120;

    float sacc[2][8][4];
    #pragma unroll
    for (int i = 0; i < 2; i++)
        #pragma unroll
        for (int j = 0; j < 8; j++)
            #pragma unroll
            for (int q = 0; q < 4; q++) sacc[i][j][q] = 0.0f;

    #pragma unroll
    for (int kc = 0; kc < 2; kc++) {
        uint32_t a[2][4];
        #pragma unroll
        for (int tm = 0; tm < 2; tm++)
            ldsm4(a[tm][0], a[tm][1], a[tm][2], a[tm][3],
                  (uint32_t)__cvta_generic_to_shared(Q + (half * 32 + tm * 16 + (mat & 1) * 8 + l7) * 80 + kc * 32 + (mat >> 1) * 16));
        uint32_t b[4][4];
        #pragma unroll
        for (int tn2 = 0; tn2 < 4; tn2++)
            ldsm4(b[tn2][0], b[tn2][1], b[tn2][2], b[tn2][3],
                  (uint32_t)__cvta_generic_to_shared(Kp + (tn2 * 16 + (mat >> 1) * 8 + l7) * 80 + kc * 32 + (mat & 1) * 16));
        #pragma unroll
        for (int tm = 0; tm < 2; tm++)
            #pragma unroll
            for (int tn = 0; tn < 8; tn++)
                mma16816(sacc[tm][tn], a[tm], b[tn >> 1][(tn & 1) * 2], b[tn >> 1][(tn & 1) * 2 + 1]);
    }

    const float scale = 0.17677669529663687f;
    uint32_t pa[2][4][4], pl[2][4][4];
    #pragma unroll
    for (int tm = 0; tm < 2; tm++) {
        #pragma unroll
        for (int slot = 0; slot < 2; slot++) {
            int n = half * 32 + tm * 16 + gr + slot * 8;
            bool valid = n < 49;
            int i1 = 0, j1 = 0, regn = 0;
            if (valid) { i1 = i2t[n]; j1 = j2t[n]; regn = regs[n]; }
            float vv[16];
            float mx = -1e30f;
            #pragma unroll
            for (int tn = 0; tn < 8; tn++) {
                #pragma unroll
                for (int e = 0; e < 2; e++) {
                    int m = tn * 8 + gc + e;
                    float v = -1e30f;
                    if (valid && m < 49) {
                        v = sacc[tm][tn][slot * 2 + e] * scale
                          + rp[h * 169 + (i1 - i2t[m] + 6) * 13 + (j1 - j2t[m] + 6)];
                        if (regs[m] != regn) v -= 100.0f;
                    }
                    vv[tn * 2 + e] = v;
                    mx = fmaxf(mx, v);
                }
            }
            mx = fmaxf(mx, __shfl_xor_sync(0xFFFFFFFFu, mx, 1));
            mx = fmaxf(mx, __shfl_xor_sync(0xFFFFFFFFu, mx, 2));
            float sum = 0.0f;
            #pragma unroll
            for (int i = 0; i < 16; i++) { vv[i] = __expf(vv[i] - mx); sum += vv[i]; }
            sum += __shfl_xor_sync(0xFFFFFFFFu, sum, 1);
            sum += __shfl_xor_sync(0xFFFFFFFFu, sum, 2);
            float inv = valid ? __frcp_rn(sum) : 0.0f;
            #pragma unroll
            for (int tn = 0; tn < 8; tn++) {
                float p0 = vv[tn * 2] * inv, p1 = vv[tn * 2 + 1] * inv;
                uint32_t u = pack_bf2(p0, p1);
                pa[tm][tn >> 1][(tn & 1) * 2 + slot] = u;
                float h0 = __uint_as_float(u << 16), h1 = __uint_as_float(u & 0xFFFF0000u);
                pl[tm][tn >> 1][(tn & 1) * 2 + slot] = pack_bf2(p0 - h0, p1 - h1);
            }
        }
    }

    float oacc[2][4][4];
    #pragma unroll
    for (int i = 0; i < 2; i++)
        #pragma unroll
        for (int j = 0; j < 4; j++)
            #pragma unroll
            for (int q = 0; q < 4; q++) oacc[i][j][q] = 0.0f;

    #pragma unroll
    for (int kk = 0; kk < 4; kk++) {
        uint32_t bh[2][4], bl[2][4];
        #pragma unroll
        for (int dd = 0; dd < 2; dd++) {
            ldsm4t(bh[dd][0], bh[dd][1], bh[dd][2], bh[dd][3],
                   (uint32_t)__cvta_generic_to_shared(Vp + (kk * 16 + (mat & 1) * 8 + l7) * 80 + dd * 32 + (mat >> 1) * 16));
            ldsm4t(bl[dd][0], bl[dd][1], bl[dd][2], bl[dd][3],
                   (uint32_t)__cvta_generic_to_shared(Vl + (kk * 16 + (mat & 1) * 8 + l7) * 80 + dd * 32 + (mat >> 1) * 16));
        }
        #pragma unroll
        for (int tm = 0; tm < 2; tm++) {
            #pragma unroll
            for (int dd = 0; dd < 2; dd++) {
                mma16816(oacc[tm][dd * 2 + 0], pa[tm][kk], bh[dd][0], bh[dd][1]);
                mma16816(oacc[tm][dd * 2 + 0], pl[tm][kk], bh[dd][0], bh[dd][1]);
                mma16816(oacc[tm][dd * 2 + 0], pa[tm][kk], bl[dd][0], bl[dd][1]);
                mma16816(oacc[tm][dd * 2 + 1], pa[tm][kk], bh[dd][2], bh[dd][3]);
                mma16816(oacc[tm][dd * 2 + 1], pl[tm][kk], bh[dd][2], bh[dd][3]);
                mma16816(oacc[tm][dd * 2 + 1], pa[tm][kk], bl[dd][2], bl[dd][3]);
            }
        }
    }

    #pragma unroll
    for (int tm = 0; tm < 2; tm++) {
        int n0 = half * 32 + tm * 16 + gr;
        #pragma unroll
        for (int dt = 0; dt < 4; dt++) {
            int col = h * 32 + dt * 8 + gc;
            if (n0 < 49)
                *(__nv_bfloat162*)(outw + ((size_t)widx * 49 + n0) * 128 + col) =
                    __floats2bfloat162_rn(oacc[tm][dt][0], oacc[tm][dt][1]);
            if (n0 + 8 < 49)
                *(__nv_bfloat162*)(outw + ((size_t)widx * 49 + n0 + 8) * 128 + col) =
                    __floats2bfloat162_rn(oacc[tm][dt][2], oacc[tm][dt][3]);
        }
    }
}

// ---------------- launch ----------------
#define FUSED_SMEM 73728
#define ATTN_SMEM 85008

extern "C" void kernel_launch(void* const* d_in, const int* in_sizes, int n_in,
                              void* d_out, int out_size) {
    const float* x      = (const float*)d_in[0];
    const float* n1g    = (const float*)d_in[1];
    const float* n1b    = (const float*)d_in[2];
    const float* qkv_w  = (const float*)d_in[3];
    const float* qkv_b  = (const float*)d_in[4];
    const float* proj_w = (const float*)d_in[5];
    const float* proj_b = (const float*)d_in[6];
    const float* rpb    = (const float*)d_in[7];
    const float* n2g    = (const float*)d_in[8];
    const float* n2b    = (const float*)d_in[9];
    const float* fc1_w  = (const float*)d_in[10];
    const float* fc1_b  = (const float*)d_in[11];
    const float* fc2_w  = (const float*)d_in[12];
    const float* fc2_b  = (const float*)d_in[13];
    float* out = (float*)d_out;

    __nv_bfloat16 *qkvb, *vlo, *attnb, *wq, *wp, *w1, *w2;
    cudaGetSymbolAddress((void**)&qkvb, g_qkv);
    cudaGetSymbolAddress((void**)&vlo,  g_vlo);
    cudaGetSymbolAddress((void**)&attnb,g_attn);
    cudaGetSymbolAddress((void**)&wq,   g_wq);
    cudaGetSymbolAddress((void**)&wp,   g_wp);
    cudaGetSymbolAddress((void**)&w1,   g_w1);
    cudaGetSymbolAddress((void**)&w2,   g_w2);

    cudaFuncSetAttribute((const void*)qkv_fused, cudaFuncAttributeMaxDynamicSharedMemorySize, FUSED_SMEM);
    cudaFuncSetAttribute((const void*)attn_kernel, cudaFuncAttributeMaxDynamicSharedMemorySize, ATTN_SMEM);
    cudaFuncSetAttribute((const void*)mlp_fused, cudaFuncAttributeMaxDynamicSharedMemorySize, MLP_SMEM);

    // 1. all weight conversions in one launch
    f2bf_all<<<192, 256>>>(qkv_w, proj_w, fc1_w, fc2_w, wq, wp, w1, w2);
    // 2. fused LN1 + shift/window gather + QKV GEMM -> bf16 qkv (+ V lo plane)
    qkv_fused<<<MROWS / 128, 256, FUSED_SMEM>>>(x, n1g, n1b, wq, qkv_b, qkvb, vlo);
    // 3. tensor-core window attention (split P/V) -> bf16
    attn_kernel<<<NWB, 256, ATTN_SMEM>>>(qkvb, vlo, rpb, attnb);
    // 4. fused proj + resid + LN2 + fc1 + GELU + fc2 + resid -> out (3-buf ring, 1 sync/step)
    mlp_fused<<<MROWS / 64, 128, MLP_SMEM>>>(attnb, x, wp, proj_b, n2g, n2b,
                                             w1, fc1_b, w2, fc2_b, out);
}

// round 16
// speedup vs baseline: 1.2367x; 1.2367x over previous
#include <cuda_runtime.h>
#include <cuda_bf16.h>
#include <stdint.h>
#include <math.h>

// ---------------- problem constants ----------------
#define BATCH 64
#define HDIM 56
#define WDIM 56
#define CDIM 128
#define NHEAD 4
#define WSZ 7
#define SHIFT 3
#define NTOK 49
#define NWIN 64
#define NWB (BATCH * NWIN)
#define MROWS (NWB * NTOK)   // 200704
#define HID 512

// ---------------- scratch ----------------
__device__ __align__(256) __nv_bfloat16 g_qkv[(size_t)MROWS * 3 * CDIM];
__device__ __align__(256) __nv_bfloat16 g_vlo[(size_t)MROWS * CDIM];
__device__ __align__(256) __nv_bfloat16 g_attn[(size_t)MROWS * CDIM];
__device__ __align__(256) __nv_bfloat16 g_wq[3 * CDIM * CDIM];
__device__ __align__(256) __nv_bfloat16 g_wp[CDIM * CDIM];
__device__ __align__(256) __nv_bfloat16 g_w1[HID * CDIM];
__device__ __align__(256) __nv_bfloat16 g_w2[CDIM * HID];

// ---------------- tensor-core helpers ----------------
__device__ __forceinline__ void ldsm4(uint32_t& r0, uint32_t& r1, uint32_t& r2, uint32_t& r3,
                                      uint32_t addr) {
    asm volatile("ldmatrix.sync.aligned.m8n8.x4.shared.b16 {%0,%1,%2,%3}, [%4];"
                 : "=r"(r0), "=r"(r1), "=r"(r2), "=r"(r3) : "r"(addr));
}
__device__ __forceinline__ void ldsm4t(uint32_t& r0, uint32_t& r1, uint32_t& r2, uint32_t& r3,
                                       uint32_t addr) {
    asm volatile("ldmatrix.sync.aligned.m8n8.x4.trans.shared.b16 {%0,%1,%2,%3}, [%4];"
                 : "=r"(r0), "=r"(r1), "=r"(r2), "=r"(r3) : "r"(addr));
}
__device__ __forceinline__ void mma16816(float* c, const uint32_t* a, uint32_t b0, uint32_t b1) {
    asm volatile("mma.sync.aligned.m16n8k16.row.col.f32.bf16.bf16.f32 "
                 "{%0,%1,%2,%3}, {%4,%5,%6,%7}, {%8,%9}, {%0,%1,%2,%3};"
                 : "+f"(c[0]), "+f"(c[1]), "+f"(c[2]), "+f"(c[3])
                 : "r"(a[0]), "r"(a[1]), "r"(a[2]), "r"(a[3]), "r"(b0), "r"(b1));
}
__device__ __forceinline__ uint32_t pack_bf2(float a, float b) {
    __nv_bfloat162 t = __floats2bfloat162_rn(a, b);
    return *(uint32_t*)&t;
}
#define CP_ASYNC16(dst, src) asm volatile("cp.async.cg.shared.global [%0], [%1], 16;" :: "r"(dst), "l"(src))
#define CP_COMMIT() asm volatile("cp.async.commit_group;")

// padded-tile micro-step (144B stride) — used by qkv_fused
__device__ __forceinline__ void mma_tile(const unsigned char* sa, const unsigned char* sb,
                                         int wm, int wn, int lane, float acc[2][8][4]) {
    const int mat = lane >> 3, l7 = lane & 7;
    #pragma unroll
    for (int ks = 0; ks < 4; ks++) {
        const int kc = ks * 2;
        uint32_t a[2][4];
        #pragma unroll
        for (int tm = 0; tm < 2; tm++) {
            int r = wm * 32 + tm * 16 + (mat & 1) * 8 + l7;
            int c = kc + (mat >> 1);
            ldsm4(a[tm][0], a[tm][1], a[tm][2], a[tm][3],
                  (uint32_t)__cvta_generic_to_shared(sa + r * 144 + c * 16));
        }
        uint32_t b[4][4];
        #pragma unroll
        for (int tn2 = 0; tn2 < 4; tn2++) {
            int n = wn * 64 + tn2 * 16 + (mat >> 1) * 8 + l7;
            int c = kc + (mat & 1);
            ldsm4(b[tn2][0], b[tn2][1], b[tn2][2], b[tn2][3],
                  (uint32_t)__cvta_generic_to_shared(sb + n * 144 + c * 16));
        }
        #pragma unroll
        for (int tm = 0; tm < 2; tm++)
            #pragma unroll
            for (int tn = 0; tn < 8; tn++)
                mma16816(acc[tm][tn], a[tm], b[tn >> 1][(tn & 1) * 2], b[tn >> 1][(tn & 1) * 2 + 1]);
    }
}

// swizzled-tile micro-step (128B stride, chunk ^= row&7) — used by mlp_fused
__device__ __forceinline__ void mma_tile_sw(const unsigned char* sa, const unsigned char* sb,
                                            int wm, int wn, int lane, float acc[2][8][4]) {
    const int mat = lane >> 3, l7 = lane & 7;
    #pragma unroll
    for (int ks = 0; ks < 4; ks++) {
        const int kc = ks * 2;
        uint32_t a[2][4];
        #pragma unroll
        for (int tm = 0; tm < 2; tm++) {
            int r = wm * 32 + tm * 16 + (mat & 1) * 8 + l7;
            int c = kc + (mat >> 1);
            ldsm4(a[tm][0], a[tm][1], a[tm][2], a[tm][3],
                  (uint32_t)__cvta_generic_to_shared(sa + r * 128 + ((c ^ (r & 7)) * 16)));
        }
        uint32_t b[4][4];
        #pragma unroll
        for (int tn2 = 0; tn2 < 4; tn2++) {
            int n = wn * 64 + tn2 * 16 + (mat >> 1) * 8 + l7;
            int c = kc + (mat & 1);
            ldsm4(b[tn2][0], b[tn2][1], b[tn2][2], b[tn2][3],
                  (uint32_t)__cvta_generic_to_shared(sb + n * 128 + ((c ^ (n & 7)) * 16)));
        }
        #pragma unroll
        for (int tm = 0; tm < 2; tm++)
            #pragma unroll
            for (int tn = 0; tn < 8; tn++)
                mma16816(acc[tm][tn], a[tm], b[tn >> 1][(tn & 1) * 2], b[tn >> 1][(tn & 1) * 2 + 1]);
    }
}

// ---------------- fp32 -> bf16 all four weights, one launch ----------------
__global__ void f2bf_all(const float* __restrict__ wq, const float* __restrict__ wp,
                         const float* __restrict__ w1, const float* __restrict__ w2,
                         __nv_bfloat16* oq, __nv_bfloat16* op,
                         __nv_bfloat16* o1, __nv_bfloat16* o2) {
    int i = blockIdx.x * 256 + threadIdx.x;   // float4 index; total 49152
    const float* src; __nv_bfloat16* dst; int off;
    if (i < 12288)      { src = wq; dst = oq; off = i; }
    else if (i < 16384) { src = wp; dst = op; off = i - 12288; }
    else if (i < 32768) { src = w1; dst = o1; off = i - 16384; }
    else                { src = w2; dst = o2; off = i - 32768; }
    float4 v = ((const float4*)src)[off];
    __nv_bfloat162* o = ((__nv_bfloat162*)dst) + off * 2;
    o[0] = __floats2bfloat162_rn(v.x, v.y);
    o[1] = __floats2bfloat162_rn(v.z, v.w);
}

// ---------------- fused LN1(+shift/window gather) + QKV GEMM ----------------
// smem: A0 @0, A1 @18432, Bbuf0 @36864, Bbuf1 @55296. total 73728.
__global__ void __launch_bounds__(256, 2)
qkv_fused(const float* __restrict__ x, const float* __restrict__ g1, const float* __restrict__ b1,
          const __nv_bfloat16* __restrict__ W, const float* __restrict__ bias,
          __nv_bfloat16* __restrict__ out, __nv_bfloat16* __restrict__ vlo) {
    extern __shared__ unsigned char smem[];
    const int tid = threadIdx.x;
    const int bR = blockIdx.x;
    const int warp = tid >> 5, lane = tid & 31;
    const int wm = warp & 3, wn = warp >> 2;
    const int ldrow = tid >> 3, ldpos = tid & 7;

    auto loadB = [&](int buf, int nt, int kt) {
        unsigned char* sb = smem + 36864 + buf * 18432;
        #pragma unroll
        for (int it = 0; it < 4; it++) {
            int row = ldrow + it * 32;
            uint32_t d = (uint32_t)__cvta_generic_to_shared(sb + row * 144 + ldpos * 16);
            CP_ASYNC16(d, W + (size_t)(nt * 128 + row) * 128 + kt * 64 + ldpos * 8);
        }
        CP_COMMIT();
    };

    loadB(0, 0, 0);
    loadB(1, 0, 1);

    // LN1 + gather into A tiles (warp w -> rows w*16..w*16+15)
    {
        float4 gv = ((const float4*)g1)[lane & 31];
        float4 bv = ((const float4*)b1)[lane & 31];
        unsigned char* At = smem + ((lane & 16) ? 18432 : 0);
        int off = (lane & 15) * 8;
        #pragma unroll 2
        for (int t = 0; t < 16; t++) {
            int row = warp * 16 + t;
            int r = bR * 128 + row;
            int widx = r / NTOK, n = r - widx * NTOK;
            int b = widx >> 6, wi = widx & 63;
            int wh = wi >> 3, ww = wi & 7;
            int i = n / 7, j = n - i * 7;
            int sh = wh * 7 + i + SHIFT; if (sh >= HDIM) sh -= HDIM;
            int sw = ww * 7 + j + SHIFT; if (sw >= WDIM) sw -= WDIM;
            long srow = (long)b * (HDIM * WDIM) + sh * WDIM + sw;
            float4 v = ((const float4*)(x + srow * (long)CDIM))[lane];
            float s = v.x + v.y + v.z + v.w;
            float sq = v.x * v.x + v.y * v.y + v.z * v.z + v.w * v.w;
            #pragma unroll
            for (int o = 16; o; o >>= 1) {
                s  += __shfl_xor_sync(0xFFFFFFFFu, s, o);
                sq += __shfl_xor_sync(0xFFFFFFFFu, sq, o);
            }
            float mu = s * (1.0f / 128.0f);
            float var = sq * (1.0f / 128.0f) - mu * mu;
            float inv = rsqrtf(var + 1e-5f);
            float r0 = (v.x - mu) * inv * gv.x + bv.x;
            float r1 = (v.y - mu) * inv * gv.y + bv.y;
            float r2 = (v.z - mu) * inv * gv.z + bv.z;
            float r3 = (v.w - mu) * inv * gv.w + bv.w;
            *(uint32_t*)(At + row * 144 + off)     = pack_bf2(r0, r1);
            *(uint32_t*)(At + row * 144 + off + 4) = pack_bf2(r2, r3);
        }
    }

    const int gr = lane >> 2, gc = (lane & 3) * 2;
    for (int nt = 0; nt < 3; nt++) {
        float acc[2][8][4];
        #pragma unroll
        for (int i = 0; i < 2; i++)
            #pragma unroll
            for (int j = 0; j < 8; j++)
                #pragma unroll
                for (int q = 0; q < 4; q++) acc[i][j][q] = 0.0f;
        #pragma unroll
        for (int kt = 0; kt < 2; kt++) {
            int idx = nt * 2 + kt;
            if (idx < 5) asm volatile("cp.async.wait_group 1;");
            else         asm volatile("cp.async.wait_group 0;");
            __syncthreads();
            mma_tile(smem + kt * 18432, smem + 36864 + (idx & 1) * 18432, wm, wn, lane, acc);
            __syncthreads();
            if (idx + 2 < 6) loadB(idx & 1, (idx + 2) >> 1, (idx + 2) & 1);
        }
        // epilogue: bias + bf16 store (nt==2 also writes V residual plane)
        #pragma unroll
        for (int tm = 0; tm < 2; tm++) {
            #pragma unroll
            for (int tn = 0; tn < 8; tn++) {
                int col = nt * 128 + wn * 64 + tn * 8 + gc;
                float bs0 = bias[col], bs1 = bias[col + 1];
                int row0 = bR * 128 + wm * 32 + tm * 16 + gr;
                float v0 = acc[tm][tn][0] + bs0, v1 = acc[tm][tn][1] + bs1;
                float v2 = acc[tm][tn][2] + bs0, v3 = acc[tm][tn][3] + bs1;
                uint32_t u0 = pack_bf2(v0, v1), u1 = pack_bf2(v2, v3);
                *(uint32_t*)(out + (size_t)row0 * 384 + col) = u0;
                *(uint32_t*)(out + (size_t)(row0 + 8) * 384 + col) = u1;
                if (nt == 2) {
                    int lc = col - 256;
                    float h0 = __uint_as_float(u0 << 16), h1 = __uint_as_float(u0 & 0xFFFF0000u);
                    float h2 = __uint_as_float(u1 << 16), h3 = __uint_as_float(u1 & 0xFFFF0000u);
                    *(uint32_t*)(vlo + (size_t)row0 * CDIM + lc) = pack_bf2(v0 - h0, v1 - h1);
                    *(uint32_t*)(vlo + (size_t)(row0 + 8) * CDIM + lc) = pack_bf2(v2 - h2, v3 - h3);
                }
            }
        }
    }
}

// ---------------- fused second half, 64-row CTA x 128 threads, 2 CTAs/SM ----------------
// proj + resid + LN2 + fc1 + GELU + fc2 + resid. Swizzled tiles (128B stride),
// 3-buffer W ring -> ONE sync per 64-K step; resid prefetched into swizzled f32 x1 stash.
// smem (raw 114688 = 112KB exactly -> 2 CTAs/SM):
//   A/xn2 sub0 @0, sub1 @8192; W ring @16384 (3x16384); h @65536 (2x8192);
//   red overlaid @65536 (proj epi only); rowmap overlaid @66560;
//   x1 f32 swizzled [64][128] @81920 (32768).
#define MG_W0 16384
#define MG_H0 65536
#define MG_RED 65536
#define MG_ROWMAP 66560
#define MG_X1 81920
#define MLP_SMEM 114688

// swizzled f32 x1 address for (row, col), col even: float2-aligned
__device__ __forceinline__ float* x1addr(unsigned char* smem, int r, int c) {
    return (float*)(smem + MG_X1 + r * 512 + (((c >> 2) ^ (r & 7)) << 4) + (c & 3) * 4);
}

__global__ void __launch_bounds__(128, 2)
mlp_fused(const __nv_bfloat16* __restrict__ A, const float* __restrict__ resid,
          const __nv_bfloat16* __restrict__ Wp, const float* __restrict__ bp,
          const float* __restrict__ g2, const float* __restrict__ b2,
          const __nv_bfloat16* __restrict__ W1, const float* __restrict__ b1,
          const __nv_bfloat16* __restrict__ W2, const float* __restrict__ b2b,
          float* __restrict__ out) {
    extern __shared__ unsigned char smem[];
    int* rowmap = (int*)(smem + MG_ROWMAP);
    float2* red = (float2*)(smem + MG_RED);
    const int tid = threadIdx.x;
    const int bR = blockIdx.x;
    const int warp = tid >> 5, lane = tid & 31;
    const int wm = warp & 1, wn = warp >> 1;   // 2x2 warp grid, warp tile 32x64
    const int ldrow = tid >> 3, ldpos = tid & 7;
    const int gr = lane >> 2, gc = (lane & 3) * 2;

    if (tid < 64) {
        int r = bR * 64 + tid;
        int b = r / (HDIM * WDIM);
        int l = r - b * (HDIM * WDIM);
        int h = l / WDIM, w = l - h * WDIM;
        int sh = h - SHIFT; if (sh < 0) sh += HDIM;
        int sw = w - SHIFT; if (sw < 0) sw += WDIM;
        int wh = sh / 7, i = sh - wh * 7;
        int ww = sw / 7, j = sw - ww * 7;
        rowmap[tid] = ((b * 64 + wh * 8 + ww) * 49 + i * 7 + j);
    }
    __syncthreads();

    // A prefetch (gathered, swizzled) + resid tile prefetch (swizzled f32), one group
    #pragma unroll
    for (int kt = 0; kt < 2; kt++)
        #pragma unroll
        for (int it = 0; it < 4; it++) {
            int row = ldrow + it * 16;
            uint32_t d = (uint32_t)__cvta_generic_to_shared(
                smem + kt * 8192 + row * 128 + ((ldpos ^ (row & 7)) * 16));
            CP_ASYNC16(d, A + (size_t)rowmap[row] * CDIM + kt * 64 + ldpos * 8);
        }
    #pragma unroll
    for (int i = 0; i < 16; i++) {
        int idx = tid + i * 128;               // 2048 16B chunks: 64 rows x 32 chunks
        int row = idx >> 5, c = idx & 31;
        uint32_t d = (uint32_t)__cvta_generic_to_shared(
            smem + MG_X1 + row * 512 + ((c ^ (row & 7)) * 16));
        CP_ASYNC16(d, resid + ((size_t)(bR * 64 + row)) * CDIM + c * 4);
    }
    CP_COMMIT();

    // weight tile stream into 3-buffer ring: s=0,1 proj; per nt: 2x W1, 2x W2
    auto loadW = [&](int s) {
        const __nv_bfloat16* base; int ld;
        if (s < 2) { base = Wp + s * 64; ld = 128; }
        else {
            int t = s - 2, nt = t >> 2, q = t & 3;
            if (q < 2) { base = W1 + (size_t)(nt * 128) * 128 + q * 64; ld = 128; }
            else       { base = W2 + nt * 128 + (q - 2) * 64; ld = 512; }
        }
        unsigned char* sb = smem + MG_W0 + (s % 3) * 16384;
        #pragma unroll
        for (int it = 0; it < 8; it++) {
            int row = ldrow + it * 16;
            uint32_t d = (uint32_t)__cvta_generic_to_shared(
                sb + row * 128 + ((ldpos ^ (row & 7)) * 16));
            CP_ASYNC16(d, base + (size_t)row * ld + ldpos * 8);
        }
        CP_COMMIT();
    };
    loadW(0); loadW(1);

    // one-sync step: wait(s) -> sync -> issue load(s+2) -> mma(s)
    auto stepHead = [&](int s) {
        if (s < 17) asm volatile("cp.async.wait_group 1;");
        else        asm volatile("cp.async.wait_group 0;");
        __syncthreads();
        if (s + 2 < 18) loadW(s + 2);
    };

    float acc2[2][8][4];
    #pragma unroll
    for (int i = 0; i < 2; i++)
        #pragma unroll
        for (int j = 0; j < 8; j++)
            #pragma unroll
            for (int q = 0; q < 4; q++) acc2[i][j][q] = 0.0f;

    // ---- proj GEMM (steps 0,1) ----
    {
        float acc1[2][8][4];
        #pragma unroll
        for (int i = 0; i < 2; i++)
            #pragma unroll
            for (int j = 0; j < 8; j++)
                #pragma unroll
                for (int q = 0; q < 4; q++) acc1[i][j][q] = 0.0f;
        #pragma unroll
        for (int kt = 0; kt < 2; kt++) {
            int s = kt;
            stepHead(s);
            mma_tile_sw(smem + kt * 8192, smem + MG_W0 + (s % 3) * 16384, wm, wn, lane, acc1);
        }
        // epilogue: + bias + resid(smem) -> x1 (same slots); row stats; LN2 -> xn2 (A tiles)
        float psum[2][2], psq[2][2];
        #pragma unroll
        for (int tm = 0; tm < 2; tm++)
            #pragma unroll
            for (int sl = 0; sl < 2; sl++) { psum[tm][sl] = 0.0f; psq[tm][sl] = 0.0f; }
        #pragma unroll
        for (int tm = 0; tm < 2; tm++) {
            #pragma unroll
            for (int tn = 0; tn < 8; tn++) {
                int col = wn * 64 + tn * 8 + gc;
                float bs0 = bp[col], bs1 = bp[col + 1];
                int lrow0 = wm * 32 + tm * 16 + gr;
                float2 r0 = *(const float2*)x1addr(smem, lrow0, col);
                float2 r1 = *(const float2*)x1addr(smem, lrow0 + 8, col);
                float v0 = acc1[tm][tn][0] + bs0 + r0.x;
                float v1 = acc1[tm][tn][1] + bs1 + r0.y;
                float v2 = acc1[tm][tn][2] + bs0 + r1.x;
                float v3 = acc1[tm][tn][3] + bs1 + r1.y;
                acc1[tm][tn][0] = v0; acc1[tm][tn][1] = v1;
                acc1[tm][tn][2] = v2; acc1[tm][tn][3] = v3;
                *(float2*)x1addr(smem, lrow0, col) = make_float2(v0, v1);
                *(float2*)x1addr(smem, lrow0 + 8, col) = make_float2(v2, v3);
                psum[tm][0] += v0 + v1;  psq[tm][0] += v0 * v0 + v1 * v1;
                psum[tm][1] += v2 + v3;  psq[tm][1] += v2 * v2 + v3 * v3;
            }
        }
        #pragma unroll
        for (int tm = 0; tm < 2; tm++)
            #pragma unroll
            for (int sl = 0; sl < 2; sl++) {
                float s = psum[tm][sl], q = psq[tm][sl];
                s += __shfl_xor_sync(0xFFFFFFFFu, s, 1); q += __shfl_xor_sync(0xFFFFFFFFu, q, 1);
                s += __shfl_xor_sync(0xFFFFFFFFu, s, 2); q += __shfl_xor_sync(0xFFFFFFFFu, q, 2);
                if ((lane & 3) == 0) red[wn * 64 + wm * 32 + tm * 16 + sl * 8 + gr] = make_float2(s, q);
            }
        __syncthreads();    // red ready; also: all warps done reading A tiles (mma step 1)
        #pragma unroll
        for (int tm = 0; tm < 2; tm++) {
            #pragma unroll
            for (int sl = 0; sl < 2; sl++) {
                int lrow = wm * 32 + tm * 16 + sl * 8 + gr;
                float2 t0 = red[lrow], t1 = red[64 + lrow];
                float mu = (t0.x + t1.x) * (1.0f / 128.0f);
                float var = (t0.y + t1.y) * (1.0f / 128.0f) - mu * mu;
                float inv = rsqrtf(var + 1e-5f);
                #pragma unroll
                for (int tn = 0; tn < 8; tn++) {
                    int col = wn * 64 + tn * 8 + gc;
                    float v0 = acc1[tm][tn][sl * 2 + 0], v1 = acc1[tm][tn][sl * 2 + 1];
                    float n0 = (v0 - mu) * inv * g2[col] + b2[col];
                    float n1 = (v1 - mu) * inv * g2[col + 1] + b2[col + 1];
                    // xn2 -> A tiles (swizzled layout)
                    int ch = (col & 63) >> 3;
                    *(uint32_t*)(smem + (col >> 6) * 8192 + lrow * 128
                                 + ((ch ^ (lrow & 7)) * 16) + (col & 7) * 2) = pack_bf2(n0, n1);
                }
            }
        }
        // no extra sync: step 2's head sync orders xn2 writes before reads
    }

    // ---- MLP: interleaved fc1(nt) -> h tile -> fc2 partial ----
    const float is2 = 0.70710678118654752f;
    for (int nt = 0; nt < 4; nt++) {
        float acc1[2][8][4];
        #pragma unroll
        for (int i = 0; i < 2; i++)
            #pragma unroll
            for (int j = 0; j < 8; j++)
                #pragma unroll
                for (int q = 0; q < 4; q++) acc1[i][j][q] = 0.0f;
        #pragma unroll
        for (int kt = 0; kt < 2; kt++) {
            int s = 2 + nt * 4 + kt;
            stepHead(s);
            mma_tile_sw(smem + kt * 8192, smem + MG_W0 + (s % 3) * 16384, wm, wn, lane, acc1);
        }
        // h epilogue: gelu(acc1 + b1) -> h tiles (swizzled)
        #pragma unroll
        for (int tm = 0; tm < 2; tm++) {
            #pragma unroll
            for (int tn = 0; tn < 8; tn++) {
                int col = wn * 64 + tn * 8 + gc;          // local 0..127
                int colg = nt * 128 + col;
                float bs0 = b1[colg], bs1 = b1[colg + 1];
                int lrow0 = wm * 32 + tm * 16 + gr;
                float v0 = acc1[tm][tn][0] + bs0, v1 = acc1[tm][tn][1] + bs1;
                float v2 = acc1[tm][tn][2] + bs0, v3 = acc1[tm][tn][3] + bs1;
                v0 = 0.5f * v0 * (1.0f + erff(v0 * is2));
                v1 = 0.5f * v1 * (1.0f + erff(v1 * is2));
                v2 = 0.5f * v2 * (1.0f + erff(v2 * is2));
                v3 = 0.5f * v3 * (1.0f + erff(v3 * is2));
                int ch = (col & 63) >> 3;
                int base = MG_H0 + (col >> 6) * 8192 + (col & 7) * 2;
                *(uint32_t*)(smem + base + lrow0 * 128 + ((ch ^ (lrow0 & 7)) * 16)) = pack_bf2(v0, v1);
                int lr1 = lrow0 + 8;
                *(uint32_t*)(smem + base + lr1 * 128 + ((ch ^ (lr1 & 7)) * 16)) = pack_bf2(v2, v3);
            }
        }
        // fc2 partial: next steps' head syncs order h writes before reads
        #pragma unroll
        for (int q = 0; q < 2; q++) {
            int s = 4 + nt * 4 + q;
            stepHead(s);
            mma_tile_sw(smem + MG_H0 + q * 8192, smem + MG_W0 + (s % 3) * 16384, wm, wn, lane, acc2);
        }
    }

    // ---- final epilogue: out = acc2 + b2b + x1 (all thread-local x1 slots) ----
    #pragma unroll
    for (int tm = 0; tm < 2; tm++) {
        #pragma unroll
        for (int tn = 0; tn < 8; tn++) {
            int col = wn * 64 + tn * 8 + gc;
            float bs0 = b2b[col], bs1 = b2b[col + 1];
            int lrow0 = wm * 32 + tm * 16 + gr;
            size_t grow0 = (size_t)(bR * 64 + lrow0);
            float2 x0 = *(const float2*)x1addr(smem, lrow0, col);
            float2 x1v = *(const float2*)x1addr(smem, lrow0 + 8, col);
            float v0 = acc2[tm][tn][0] + bs0, v1 = acc2[tm][tn][1] + bs1;
            float v2 = acc2[tm][tn][2] + bs0, v3 = acc2[tm][tn][3] + bs1;
            *(float2*)(out + grow0 * CDIM + col)       = make_float2(v0 + x0.x, v1 + x0.y);
            *(float2*)(out + (grow0 + 8) * CDIM + col) = make_float2(v2 + x1v.x, v3 + x1v.y);
        }
    }
}

// ---------------- tensor-core window attention, split-precision P@V ----------------
__global__ void __launch_bounds__(256)
attn_kernel(const __nv_bfloat16* __restrict__ qkv, const __nv_bfloat16* __restrict__ vlo,
            const float* __restrict__ rpb, __nv_bfloat16* __restrict__ outw) {
    extern __shared__ unsigned char sm[];
    const int widx = blockIdx.x;
    const int tid = threadIdx.x;

    #pragma unroll
    for (int it = 0; it < 12; it++) {
        int idx = it * 256 + tid;
        int c4 = idx & 3, row = (idx >> 2) & 63, h = (idx >> 8) & 3, t = idx >> 10;
        uint4 v = make_uint4(0, 0, 0, 0);
        if (row < 49)
            v = *(const uint4*)(qkv + (size_t)widx * 18816 + row * 384 + t * 128 + h * 32 + c4 * 8);
        *(uint4*)(sm + h * 15360 + t * 5120 + row * 80 + c4 * 16) = v;
    }
    #pragma unroll
    for (int it = 0; it < 4; it++) {
        int idx = it * 256 + tid;
        int c4 = idx & 3, row = (idx >> 2) & 63, h = idx >> 8;
        uint4 v = make_uint4(0, 0, 0, 0);
        if (row < 49)
            v = *(const uint4*)(vlo + ((size_t)widx * 49 + row) * 128 + h * 32 + c4 * 8);
        *(uint4*)(sm + 61440 + h * 5120 + row * 80 + c4 * 16) = v;
    }
    float* rp = (float*)(sm + 81920);
    for (int p = tid; p < 676; p += 256) rp[p] = rpb[(p % 169) * 4 + (p / 169)];
    int* regs = (int*)(sm + 84624);
    signed char* i2t = (signed char*)(sm + 84880);
    signed char* j2t = (signed char*)(sm + 84944);
    if (tid < 64) { i2t[tid] = tid / 7; j2t[tid] = tid % 7; }
    if (tid < 49) {
        int wi = widx & 63;
        int wh = wi >> 3, ww = wi & 7;
        int i = tid / 7, j = tid - i * 7;
        int grr = wh * 7 + i, gcc = ww * 7 + j;
        int rr = grr < 49 ? 0 : (grr < 53 ? 1 : 2);
        int rc = gcc < 49 ? 0 : (gcc < 53 ? 1 : 2);
        regs[tid] = rr * 3 + rc;
    }
    __syncthreads();

    const int warp = tid >> 5, lane = tid & 31;
    const int h = warp >> 1, half = warp & 1;
    const int mat = lane >> 3, l7 = lane & 7, gr = lane >> 2, gc = (lane & 3) * 2;
    const unsigned char* Q = sm + h * 15360;
    const unsigned char* Kp = Q + 5120;
    const unsigned char* Vp = Q + 10240;
    const unsigned char* Vl = sm + 61440 + h * 5120;

    float sacc[2][8][4];
    #pragma unroll
    for (int i = 0; i < 2; i++)
        #pragma unroll
        for (int j = 0; j < 8; j++)
            #pragma unroll
            for (int q = 0; q < 4; q++) sacc[i][j][q] = 0.0f;

    #pragma unroll
    for (int kc = 0; kc < 2; kc++) {
        uint32_t a[2][4];
        #pragma unroll
        for (int tm = 0; tm < 2; tm++)
            ldsm4(a[tm][0], a[tm][1], a[tm][2], a[tm][3],
                  (uint32_t)__cvta_generic_to_shared(Q + (half * 32 + tm * 16 + (mat & 1) * 8 + l7) * 80 + kc * 32 + (mat >> 1) * 16));
        uint32_t b[4][4];
        #pragma unroll
        for (int tn2 = 0; tn2 < 4; tn2++)
            ldsm4(b[tn2][0], b[tn2][1], b[tn2][2], b[tn2][3],
                  (uint32_t)__cvta_generic_to_shared(Kp + (tn2 * 16 + (mat >> 1) * 8 + l7) * 80 + kc * 32 + (mat & 1) * 16));
        #pragma unroll
        for (int tm = 0; tm < 2; tm++)
            #pragma unroll
            for (int tn = 0; tn < 8; tn++)
                mma16816(sacc[tm][tn], a[tm], b[tn >> 1][(tn & 1) * 2], b[tn >> 1][(tn & 1) * 2 + 1]);
    }

    const float scale = 0.17677669529663687f;
    uint32_t pa[2][4][4], pl[2][4][4];
    #pragma unroll
    for (int tm = 0; tm < 2; tm++) {
        #pragma unroll
        for (int slot = 0; slot < 2; slot++) {
            int n = half * 32 + tm * 16 + gr + slot * 8;
            bool valid = n < 49;
            int i1 = 0, j1 = 0, regn = 0;
            if (valid) { i1 = i2t[n]; j1 = j2t[n]; regn = regs[n]; }
            float vv[16];
            float mx = -1e30f;
            #pragma unroll
            for (int tn = 0; tn < 8; tn++) {
                #pragma unroll
                for (int e = 0; e < 2; e++) {
                    int m = tn * 8 + gc + e;
                    float v = -1e30f;
                    if (valid && m < 49) {
                        v = sacc[tm][tn][slot * 2 + e] * scale
                          + rp[h * 169 + (i1 - i2t[m] + 6) * 13 + (j1 - j2t[m] + 6)];
                        if (regs[m] != regn) v -= 100.0f;
                    }
                    vv[tn * 2 + e] = v;
                    mx = fmaxf(mx, v);
                }
            }
            mx = fmaxf(mx, __shfl_xor_sync(0xFFFFFFFFu, mx, 1));
            mx = fmaxf(mx, __shfl_xor_sync(0xFFFFFFFFu, mx, 2));
            float sum = 0.0f;
            #pragma unroll
            for (int i = 0; i < 16; i++) { vv[i] = __expf(vv[i] - mx); sum += vv[i]; }
            sum += __shfl_xor_sync(0xFFFFFFFFu, sum, 1);
            sum += __shfl_xor_sync(0xFFFFFFFFu, sum, 2);
            float inv = valid ? __frcp_rn(sum) : 0.0f;
            #pragma unroll
            for (int tn = 0; tn < 8; tn++) {
                float p0 = vv[tn * 2] * inv, p1 = vv[tn * 2 + 1] * inv;
                uint32_t u = pack_bf2(p0, p1);
                pa[tm][tn >> 1][(tn & 1) * 2 + slot] = u;
                float h0 = __uint_as_float(u << 16), h1 = __uint_as_float(u & 0xFFFF0000u);
                pl[tm][tn >> 1][(tn & 1) * 2 + slot] = pack_bf2(p0 - h0, p1 - h1);
            }
        }
    }

    float oacc[2][4][4];
    #pragma unroll
    for (int i = 0; i < 2; i++)
        #pragma unroll
        for (int j = 0; j < 4; j++)
            #pragma unroll
            for (int q = 0; q < 4; q++) oacc[i][j][q] = 0.0f;

    #pragma unroll
    for (int kk = 0; kk < 4; kk++) {
        uint32_t bh[2][4], bl[2][4];
        #pragma unroll
        for (int dd = 0; dd < 2; dd++) {
            ldsm4t(bh[dd][0], bh[dd][1], bh[dd][2], bh[dd][3],
                   (uint32_t)__cvta_generic_to_shared(Vp + (kk * 16 + (mat & 1) * 8 + l7) * 80 + dd * 32 + (mat >> 1) * 16));
            ldsm4t(bl[dd][0], bl[dd][1], bl[dd][2], bl[dd][3],
                   (uint32_t)__cvta_generic_to_shared(Vl + (kk * 16 + (mat & 1) * 8 + l7) * 80 + dd * 32 + (mat >> 1) * 16));
        }
        #pragma unroll
        for (int tm = 0; tm < 2; tm++) {
            #pragma unroll
            for (int dd = 0; dd < 2; dd++) {
                mma16816(oacc[tm][dd * 2 + 0], pa[tm][kk], bh[dd][0], bh[dd][1]);
                mma16816(oacc[tm][dd * 2 + 0], pl[tm][kk], bh[dd][0], bh[dd][1]);
                mma16816(oacc[tm][dd * 2 + 0], pa[tm][kk], bl[dd][0], bl[dd][1]);
                mma16816(oacc[tm][dd * 2 + 1], pa[tm][kk], bh[dd][2], bh[dd][3]);
                mma16816(oacc[tm][dd * 2 + 1], pl[tm][kk], bh[dd][2], bh[dd][3]);
                mma16816(oacc[tm][dd * 2 + 1], pa[tm][kk], bl[dd][2], bl[dd][3]);
            }
        }
    }

    #pragma unroll
    for (int tm = 0; tm < 2; tm++) {
        int n0 = half * 32 + tm * 16 + gr;
        #pragma unroll
        for (int dt = 0; dt < 4; dt++) {
            int col = h * 32 + dt * 8 + gc;
            if (n0 < 49)
                *(__nv_bfloat162*)(outw + ((size_t)widx * 49 + n0) * 128 + col) =
                    __floats2bfloat162_rn(oacc[tm][dt][0], oacc[tm][dt][1]);
            if (n0 + 8 < 49)
                *(__nv_bfloat162*)(outw + ((size_t)widx * 49 + n0 + 8) * 128 + col) =
                    __floats2bfloat162_rn(oacc[tm][dt][2], oacc[tm][dt][3]);
        }
    }
}

// ---------------- launch ----------------
#define FUSED_SMEM 73728
#define ATTN_SMEM 85008

extern "C" void kernel_launch(void* const* d_in, const int* in_sizes, int n_in,
                              void* d_out, int out_size) {
    const float* x      = (const float*)d_in[0];
    const float* n1g    = (const float*)d_in[1];
    const float* n1b    = (const float*)d_in[2];
    const float* qkv_w  = (const float*)d_in[3];
    const float* qkv_b  = (const float*)d_in[4];
    const float* proj_w = (const float*)d_in[5];
    const float* proj_b = (const float*)d_in[6];
    const float* rpb    = (const float*)d_in[7];
    const float* n2g    = (const float*)d_in[8];
    const float* n2b    = (const float*)d_in[9];
    const float* fc1_w  = (const float*)d_in[10];
    const float* fc1_b  = (const float*)d_in[11];
    const float* fc2_w  = (const float*)d_in[12];
    const float* fc2_b  = (const float*)d_in[13];
    float* out = (float*)d_out;

    __nv_bfloat16 *qkvb, *vlo, *attnb, *wq, *wp, *w1, *w2;
    cudaGetSymbolAddress((void**)&qkvb, g_qkv);
    cudaGetSymbolAddress((void**)&vlo,  g_vlo);
    cudaGetSymbolAddress((void**)&attnb,g_attn);
    cudaGetSymbolAddress((void**)&wq,   g_wq);
    cudaGetSymbolAddress((void**)&wp,   g_wp);
    cudaGetSymbolAddress((void**)&w1,   g_w1);
    cudaGetSymbolAddress((void**)&w2,   g_w2);

    cudaFuncSetAttribute((const void*)qkv_fused, cudaFuncAttributeMaxDynamicSharedMemorySize, FUSED_SMEM);
    cudaFuncSetAttribute((const void*)attn_kernel, cudaFuncAttributeMaxDynamicSharedMemorySize, ATTN_SMEM);
    cudaFuncSetAttribute((const void*)mlp_fused, cudaFuncAttributeMaxDynamicSharedMemorySize, MLP_SMEM);

    // 1. all weight conversions in one launch
    f2bf_all<<<192, 256>>>(qkv_w, proj_w, fc1_w, fc2_w, wq, wp, w1, w2);
    // 2. fused LN1 + shift/window gather + QKV GEMM -> bf16 qkv (+ V lo plane)
    qkv_fused<<<MROWS / 128, 256, FUSED_SMEM>>>(x, n1g, n1b, wq, qkv_b, qkvb, vlo);
    // 3. tensor-core window attention (split P/V) -> bf16
    attn_kernel<<<NWB, 256, ATTN_SMEM>>>(qkvb, vlo, rpb, attnb);
    // 4. fused proj + resid + LN2 + fc1 + GELU + fc2 + resid -> out
    //    (3-buf ring, 1 sync/step, 112KB smem exactly -> 2 CTAs/SM)
    mlp_fused<<<MROWS / 64, 128, MLP_SMEM>>>(attnb, x, wp, proj_b, n2g, n2b,
                                             w1, fc1_b, w2, fc2_b, out);
}

// round 17
// speedup vs baseline: 1.2524x; 1.0127x over previous
#include <cuda_runtime.h>
#include <cuda_bf16.h>
#include <stdint.h>
#include <math.h>

// ---------------- problem constants ----------------
#define BATCH 64
#define HDIM 56
#define WDIM 56
#define CDIM 128
#define NHEAD 4
#define WSZ 7
#define SHIFT 3
#define NTOK 49
#define NWIN 64
#define NWB (BATCH * NWIN)
#define MROWS (NWB * NTOK)   // 200704
#define HID 512

// ---------------- scratch ----------------
__device__ __align__(256) __nv_bfloat16 g_qkv[(size_t)MROWS * 3 * CDIM];
__device__ __align__(256) __nv_bfloat16 g_vlo[(size_t)MROWS * CDIM];
__device__ __align__(256) __nv_bfloat16 g_attn[(size_t)MROWS * CDIM];
__device__ __align__(256) __nv_bfloat16 g_wq[3 * CDIM * CDIM];
__device__ __align__(256) __nv_bfloat16 g_wp[CDIM * CDIM];
__device__ __align__(256) __nv_bfloat16 g_w1[HID * CDIM];
__device__ __align__(256) __nv_bfloat16 g_w2[CDIM * HID];

// ---------------- tensor-core helpers ----------------
__device__ __forceinline__ void ldsm4(uint32_t& r0, uint32_t& r1, uint32_t& r2, uint32_t& r3,
                                      uint32_t addr) {
    asm volatile("ldmatrix.sync.aligned.m8n8.x4.shared.b16 {%0,%1,%2,%3}, [%4];"
                 : "=r"(r0), "=r"(r1), "=r"(r2), "=r"(r3) : "r"(addr));
}
__device__ __forceinline__ void ldsm4t(uint32_t& r0, uint32_t& r1, uint32_t& r2, uint32_t& r3,
                                       uint32_t addr) {
    asm volatile("ldmatrix.sync.aligned.m8n8.x4.trans.shared.b16 {%0,%1,%2,%3}, [%4];"
                 : "=r"(r0), "=r"(r1), "=r"(r2), "=r"(r3) : "r"(addr));
}
__device__ __forceinline__ void mma16816(float* c, const uint32_t* a, uint32_t b0, uint32_t b1) {
    asm volatile("mma.sync.aligned.m16n8k16.row.col.f32.bf16.bf16.f32 "
                 "{%0,%1,%2,%3}, {%4,%5,%6,%7}, {%8,%9}, {%0,%1,%2,%3};"
                 : "+f"(c[0]), "+f"(c[1]), "+f"(c[2]), "+f"(c[3])
                 : "r"(a[0]), "r"(a[1]), "r"(a[2]), "r"(a[3]), "r"(b0), "r"(b1));
}
__device__ __forceinline__ uint32_t pack_bf2(float a, float b) {
    __nv_bfloat162 t = __floats2bfloat162_rn(a, b);
    return *(uint32_t*)&t;
}
#define CP_ASYNC16(dst, src) asm volatile("cp.async.cg.shared.global [%0], [%1], 16;" :: "r"(dst), "l"(src))
#define CP_COMMIT() asm volatile("cp.async.commit_group;")

// padded-tile micro-step (144B stride) — used by qkv_fused
__device__ __forceinline__ void mma_tile(const unsigned char* sa, const unsigned char* sb,
                                         int wm, int wn, int lane, float acc[2][8][4]) {
    const int mat = lane >> 3, l7 = lane & 7;
    #pragma unroll
    for (int ks = 0; ks < 4; ks++) {
        const int kc = ks * 2;
        uint32_t a[2][4];
        #pragma unroll
        for (int tm = 0; tm < 2; tm++) {
            int r = wm * 32 + tm * 16 + (mat & 1) * 8 + l7;
            int c = kc + (mat >> 1);
            ldsm4(a[tm][0], a[tm][1], a[tm][2], a[tm][3],
                  (uint32_t)__cvta_generic_to_shared(sa + r * 144 + c * 16));
        }
        uint32_t b[4][4];
        #pragma unroll
        for (int tn2 = 0; tn2 < 4; tn2++) {
            int n = wn * 64 + tn2 * 16 + (mat >> 1) * 8 + l7;
            int c = kc + (mat & 1);
            ldsm4(b[tn2][0], b[tn2][1], b[tn2][2], b[tn2][3],
                  (uint32_t)__cvta_generic_to_shared(sb + n * 144 + c * 16));
        }
        #pragma unroll
        for (int tm = 0; tm < 2; tm++)
            #pragma unroll
            for (int tn = 0; tn < 8; tn++)
                mma16816(acc[tm][tn], a[tm], b[tn >> 1][(tn & 1) * 2], b[tn >> 1][(tn & 1) * 2 + 1]);
    }
}

// swizzled-tile micro-step (128B stride, chunk ^= row&7) — used by mlp_fused
__device__ __forceinline__ void mma_tile_sw(const unsigned char* sa, const unsigned char* sb,
                                            int wm, int wn, int lane, float acc[2][8][4]) {
    const int mat = lane >> 3, l7 = lane & 7;
    #pragma unroll
    for (int ks = 0; ks < 4; ks++) {
        const int kc = ks * 2;
        uint32_t a[2][4];
        #pragma unroll
        for (int tm = 0; tm < 2; tm++) {
            int r = wm * 32 + tm * 16 + (mat & 1) * 8 + l7;
            int c = kc + (mat >> 1);
            ldsm4(a[tm][0], a[tm][1], a[tm][2], a[tm][3],
                  (uint32_t)__cvta_generic_to_shared(sa + r * 128 + ((c ^ (r & 7)) * 16)));
        }
        uint32_t b[4][4];
        #pragma unroll
        for (int tn2 = 0; tn2 < 4; tn2++) {
            int n = wn * 64 + tn2 * 16 + (mat >> 1) * 8 + l7;
            int c = kc + (mat & 1);
            ldsm4(b[tn2][0], b[tn2][1], b[tn2][2], b[tn2][3],
                  (uint32_t)__cvta_generic_to_shared(sb + n * 128 + ((c ^ (n & 7)) * 16)));
        }
        #pragma unroll
        for (int tm = 0; tm < 2; tm++)
            #pragma unroll
            for (int tn = 0; tn < 8; tn++)
                mma16816(acc[tm][tn], a[tm], b[tn >> 1][(tn & 1) * 2], b[tn >> 1][(tn & 1) * 2 + 1]);
    }
}

// ---------------- fp32 -> bf16 all four weights, one launch ----------------
__global__ void f2bf_all(const float* __restrict__ wq, const float* __restrict__ wp,
                         const float* __restrict__ w1, const float* __restrict__ w2,
                         __nv_bfloat16* oq, __nv_bfloat16* op,
                         __nv_bfloat16* o1, __nv_bfloat16* o2) {
    int i = blockIdx.x * 256 + threadIdx.x;   // float4 index; total 49152
    const float* src; __nv_bfloat16* dst; int off;
    if (i < 12288)      { src = wq; dst = oq; off = i; }
    else if (i < 16384) { src = wp; dst = op; off = i - 12288; }
    else if (i < 32768) { src = w1; dst = o1; off = i - 16384; }
    else                { src = w2; dst = o2; off = i - 32768; }
    float4 v = ((const float4*)src)[off];
    __nv_bfloat162* o = ((__nv_bfloat162*)dst) + off * 2;
    o[0] = __floats2bfloat162_rn(v.x, v.y);
    o[1] = __floats2bfloat162_rn(v.z, v.w);
}

// ---------------- fused LN1(+shift/window gather) + QKV GEMM ----------------
// 3-buffer B ring, one sync per 64-K step.
// smem: A0 @0, A1 @18432, B ring @36864 (3 x 18432). total 92160.
#define QK_SMEM 92160
__global__ void __launch_bounds__(256, 2)
qkv_fused(const float* __restrict__ x, const float* __restrict__ g1, const float* __restrict__ b1,
          const __nv_bfloat16* __restrict__ W, const float* __restrict__ bias,
          __nv_bfloat16* __restrict__ out, __nv_bfloat16* __restrict__ vlo) {
    extern __shared__ unsigned char smem[];
    const int tid = threadIdx.x;
    const int bR = blockIdx.x;
    const int warp = tid >> 5, lane = tid & 31;
    const int wm = warp & 3, wn = warp >> 2;
    const int ldrow = tid >> 3, ldpos = tid & 7;

    auto loadB = [&](int s) {                  // s = nt*2 + kt
        int nt = s >> 1, kt = s & 1;
        unsigned char* sb = smem + 36864 + (s % 3) * 18432;
        #pragma unroll
        for (int it = 0; it < 4; it++) {
            int row = ldrow + it * 32;
            uint32_t d = (uint32_t)__cvta_generic_to_shared(sb + row * 144 + ldpos * 16);
            CP_ASYNC16(d, W + (size_t)(nt * 128 + row) * 128 + kt * 64 + ldpos * 8);
        }
        CP_COMMIT();
    };

    loadB(0);
    loadB(1);

    // LN1 + gather into A tiles (warp w -> rows w*16..w*16+15)
    {
        float4 gv = ((const float4*)g1)[lane & 31];
        float4 bv = ((const float4*)b1)[lane & 31];
        unsigned char* At = smem + ((lane & 16) ? 18432 : 0);
        int off = (lane & 15) * 8;
        #pragma unroll 2
        for (int t = 0; t < 16; t++) {
            int row = warp * 16 + t;
            int r = bR * 128 + row;
            int widx = r / NTOK, n = r - widx * NTOK;
            int b = widx >> 6, wi = widx & 63;
            int wh = wi >> 3, ww = wi & 7;
            int i = n / 7, j = n - i * 7;
            int sh = wh * 7 + i + SHIFT; if (sh >= HDIM) sh -= HDIM;
            int sw = ww * 7 + j + SHIFT; if (sw >= WDIM) sw -= WDIM;
            long srow = (long)b * (HDIM * WDIM) + sh * WDIM + sw;
            float4 v = ((const float4*)(x + srow * (long)CDIM))[lane];
            float s = v.x + v.y + v.z + v.w;
            float sq = v.x * v.x + v.y * v.y + v.z * v.z + v.w * v.w;
            #pragma unroll
            for (int o = 16; o; o >>= 1) {
                s  += __shfl_xor_sync(0xFFFFFFFFu, s, o);
                sq += __shfl_xor_sync(0xFFFFFFFFu, sq, o);
            }
            float mu = s * (1.0f / 128.0f);
            float var = sq * (1.0f / 128.0f) - mu * mu;
            float inv = rsqrtf(var + 1e-5f);
            float r0 = (v.x - mu) * inv * gv.x + bv.x;
            float r1 = (v.y - mu) * inv * gv.y + bv.y;
            float r2 = (v.z - mu) * inv * gv.z + bv.z;
            float r3 = (v.w - mu) * inv * gv.w + bv.w;
            *(uint32_t*)(At + row * 144 + off)     = pack_bf2(r0, r1);
            *(uint32_t*)(At + row * 144 + off + 4) = pack_bf2(r2, r3);
        }
    }

    const int gr = lane >> 2, gc = (lane & 3) * 2;
    for (int nt = 0; nt < 3; nt++) {
        float acc[2][8][4];
        #pragma unroll
        for (int i = 0; i < 2; i++)
            #pragma unroll
            for (int j = 0; j < 8; j++)
                #pragma unroll
                for (int q = 0; q < 4; q++) acc[i][j][q] = 0.0f;
        #pragma unroll
        for (int kt = 0; kt < 2; kt++) {
            int s = nt * 2 + kt;
            if (s < 5) asm volatile("cp.async.wait_group 1;");
            else       asm volatile("cp.async.wait_group 0;");
            __syncthreads();               // orders prior reads of buffer (s+2)%3 and LN/A writes
            if (s + 2 < 6) loadB(s + 2);   // writes buffer (s-1)%3 — reads done at step s-1
            mma_tile(smem + kt * 18432, smem + 36864 + (s % 3) * 18432, wm, wn, lane, acc);
        }
        // epilogue: bias + bf16 store (nt==2 also writes V residual plane) — gmem only, no sync
        #pragma unroll
        for (int tm = 0; tm < 2; tm++) {
            #pragma unroll
            for (int tn = 0; tn < 8; tn++) {
                int col = nt * 128 + wn * 64 + tn * 8 + gc;
                float bs0 = bias[col], bs1 = bias[col + 1];
                int row0 = bR * 128 + wm * 32 + tm * 16 + gr;
                float v0 = acc[tm][tn][0] + bs0, v1 = acc[tm][tn][1] + bs1;
                float v2 = acc[tm][tn][2] + bs0, v3 = acc[tm][tn][3] + bs1;
                uint32_t u0 = pack_bf2(v0, v1), u1 = pack_bf2(v2, v3);
                *(uint32_t*)(out + (size_t)row0 * 384 + col) = u0;
                *(uint32_t*)(out + (size_t)(row0 + 8) * 384 + col) = u1;
                if (nt == 2) {
                    int lc = col - 256;
                    float h0 = __uint_as_float(u0 << 16), h1 = __uint_as_float(u0 & 0xFFFF0000u);
                    float h2 = __uint_as_float(u1 << 16), h3 = __uint_as_float(u1 & 0xFFFF0000u);
                    *(uint32_t*)(vlo + (size_t)row0 * CDIM + lc) = pack_bf2(v0 - h0, v1 - h1);
                    *(uint32_t*)(vlo + (size_t)(row0 + 8) * CDIM + lc) = pack_bf2(v2 - h2, v3 - h3);
                }
            }
        }
    }
}

// ---------------- fused second half, 64-row CTA x 128 threads, 2 CTAs/SM ----------------
// proj + resid + LN2 + fc1 + GELU + fc2 + resid. Swizzled tiles (128B stride),
// 3-buffer W ring -> ONE sync per 64-K step; resid prefetched into swizzled f32 x1 stash.
// smem (raw 114688 = 112KB exactly -> 2 CTAs/SM):
//   A/xn2 sub0 @0, sub1 @8192; W ring @16384 (3x16384); h @65536 (2x8192);
//   red overlaid @65536 (proj epi only); rowmap overlaid @66560;
//   x1 f32 swizzled [64][128] @81920 (32768).
#define MG_W0 16384
#define MG_H0 65536
#define MG_RED 65536
#define MG_ROWMAP 66560
#define MG_X1 81920
#define MLP_SMEM 114688

// swizzled f32 x1 address for (row, col), col even: float2-aligned
__device__ __forceinline__ float* x1addr(unsigned char* smem, int r, int c) {
    return (float*)(smem + MG_X1 + r * 512 + (((c >> 2) ^ (r & 7)) << 4) + (c & 3) * 4);
}

__global__ void __launch_bounds__(128, 2)
mlp_fused(const __nv_bfloat16* __restrict__ A, const float* __restrict__ resid,
          const __nv_bfloat16* __restrict__ Wp, const float* __restrict__ bp,
          const float* __restrict__ g2, const float* __restrict__ b2,
          const __nv_bfloat16* __restrict__ W1, const float* __restrict__ b1,
          const __nv_bfloat16* __restrict__ W2, const float* __restrict__ b2b,
          float* __restrict__ out) {
    extern __shared__ unsigned char smem[];
    int* rowmap = (int*)(smem + MG_ROWMAP);
    float2* red = (float2*)(smem + MG_RED);
    const int tid = threadIdx.x;
    const int bR = blockIdx.x;
    const int warp = tid >> 5, lane = tid & 31;
    const int wm = warp & 1, wn = warp >> 1;   // 2x2 warp grid, warp tile 32x64
    const int ldrow = tid >> 3, ldpos = tid & 7;
    const int gr = lane >> 2, gc = (lane & 3) * 2;

    if (tid < 64) {
        int r = bR * 64 + tid;
        int b = r / (HDIM * WDIM);
        int l = r - b * (HDIM * WDIM);
        int h = l / WDIM, w = l - h * WDIM;
        int sh = h - SHIFT; if (sh < 0) sh += HDIM;
        int sw = w - SHIFT; if (sw < 0) sw += WDIM;
        int wh = sh / 7, i = sh - wh * 7;
        int ww = sw / 7, j = sw - ww * 7;
        rowmap[tid] = ((b * 64 + wh * 8 + ww) * 49 + i * 7 + j);
    }
    __syncthreads();

    // A prefetch (gathered, swizzled) + resid tile prefetch (swizzled f32), one group
    #pragma unroll
    for (int kt = 0; kt < 2; kt++)
        #pragma unroll
        for (int it = 0; it < 4; it++) {
            int row = ldrow + it * 16;
            uint32_t d = (uint32_t)__cvta_generic_to_shared(
                smem + kt * 8192 + row * 128 + ((ldpos ^ (row & 7)) * 16));
            CP_ASYNC16(d, A + (size_t)rowmap[row] * CDIM + kt * 64 + ldpos * 8);
        }
    #pragma unroll
    for (int i = 0; i < 16; i++) {
        int idx = tid + i * 128;               // 2048 16B chunks: 64 rows x 32 chunks
        int row = idx >> 5, c = idx & 31;
        uint32_t d = (uint32_t)__cvta_generic_to_shared(
            smem + MG_X1 + row * 512 + ((c ^ (row & 7)) * 16));
        CP_ASYNC16(d, resid + ((size_t)(bR * 64 + row)) * CDIM + c * 4);
    }
    CP_COMMIT();

    // weight tile stream into 3-buffer ring: s=0,1 proj; per nt: 2x W1, 2x W2
    auto loadW = [&](int s) {
        const __nv_bfloat16* base; int ld;
        if (s < 2) { base = Wp + s * 64; ld = 128; }
        else {
            int t = s - 2, nt = t >> 2, q = t & 3;
            if (q < 2) { base = W1 + (size_t)(nt * 128) * 128 + q * 64; ld = 128; }
            else       { base = W2 + nt * 128 + (q - 2) * 64; ld = 512; }
        }
        unsigned char* sb = smem + MG_W0 + (s % 3) * 16384;
        #pragma unroll
        for (int it = 0; it < 8; it++) {
            int row = ldrow + it * 16;
            uint32_t d = (uint32_t)__cvta_generic_to_shared(
                sb + row * 128 + ((ldpos ^ (row & 7)) * 16));
            CP_ASYNC16(d, base + (size_t)row * ld + ldpos * 8);
        }
        CP_COMMIT();
    };
    loadW(0); loadW(1);

    // one-sync step: wait(s) -> sync -> issue load(s+2) -> mma(s)
    auto stepHead = [&](int s) {
        if (s < 17) asm volatile("cp.async.wait_group 1;");
        else        asm volatile("cp.async.wait_group 0;");
        __syncthreads();
        if (s + 2 < 18) loadW(s + 2);
    };

    float acc2[2][8][4];
    #pragma unroll
    for (int i = 0; i < 2; i++)
        #pragma unroll
        for (int j = 0; j < 8; j++)
            #pragma unroll
            for (int q = 0; q < 4; q++) acc2[i][j][q] = 0.0f;

    // ---- proj GEMM (steps 0,1) ----
    {
        float acc1[2][8][4];
        #pragma unroll
        for (int i = 0; i < 2; i++)
            #pragma unroll
            for (int j = 0; j < 8; j++)
                #pragma unroll
                for (int q = 0; q < 4; q++) acc1[i][j][q] = 0.0f;
        #pragma unroll
        for (int kt = 0; kt < 2; kt++) {
            int s = kt;
            stepHead(s);
            mma_tile_sw(smem + kt * 8192, smem + MG_W0 + (s % 3) * 16384, wm, wn, lane, acc1);
        }
        // epilogue: + bias + resid(smem) -> x1 (same slots); row stats; LN2 -> xn2 (A tiles)
        float psum[2][2], psq[2][2];
        #pragma unroll
        for (int tm = 0; tm < 2; tm++)
            #pragma unroll
            for (int sl = 0; sl < 2; sl++) { psum[tm][sl] = 0.0f; psq[tm][sl] = 0.0f; }
        #pragma unroll
        for (int tm = 0; tm < 2; tm++) {
            #pragma unroll
            for (int tn = 0; tn < 8; tn++) {
                int col = wn * 64 + tn * 8 + gc;
                float bs0 = bp[col], bs1 = bp[col + 1];
                int lrow0 = wm * 32 + tm * 16 + gr;
                float2 r0 = *(const float2*)x1addr(smem, lrow0, col);
                float2 r1 = *(const float2*)x1addr(smem, lrow0 + 8, col);
                float v0 = acc1[tm][tn][0] + bs0 + r0.x;
                float v1 = acc1[tm][tn][1] + bs1 + r0.y;
                float v2 = acc1[tm][tn][2] + bs0 + r1.x;
                float v3 = acc1[tm][tn][3] + bs1 + r1.y;
                acc1[tm][tn][0] = v0; acc1[tm][tn][1] = v1;
                acc1[tm][tn][2] = v2; acc1[tm][tn][3] = v3;
                *(float2*)x1addr(smem, lrow0, col) = make_float2(v0, v1);
                *(float2*)x1addr(smem, lrow0 + 8, col) = make_float2(v2, v3);
                psum[tm][0] += v0 + v1;  psq[tm][0] += v0 * v0 + v1 * v1;
                psum[tm][1] += v2 + v3;  psq[tm][1] += v2 * v2 + v3 * v3;
            }
        }
        #pragma unroll
        for (int tm = 0; tm < 2; tm++)
            #pragma unroll
            for (int sl = 0; sl < 2; sl++) {
                float s = psum[tm][sl], q = psq[tm][sl];
                s += __shfl_xor_sync(0xFFFFFFFFu, s, 1); q += __shfl_xor_sync(0xFFFFFFFFu, q, 1);
                s += __shfl_xor_sync(0xFFFFFFFFu, s, 2); q += __shfl_xor_sync(0xFFFFFFFFu, q, 2);
                if ((lane & 3) == 0) red[wn * 64 + wm * 32 + tm * 16 + sl * 8 + gr] = make_float2(s, q);
            }
        __syncthreads();    // red ready; also: all warps done reading A tiles (mma step 1)
        #pragma unroll
        for (int tm = 0; tm < 2; tm++) {
            #pragma unroll
            for (int sl = 0; sl < 2; sl++) {
                int lrow = wm * 32 + tm * 16 + sl * 8 + gr;
                float2 t0 = red[lrow], t1 = red[64 + lrow];
                float mu = (t0.x + t1.x) * (1.0f / 128.0f);
                float var = (t0.y + t1.y) * (1.0f / 128.0f) - mu * mu;
                float inv = rsqrtf(var + 1e-5f);
                #pragma unroll
                for (int tn = 0; tn < 8; tn++) {
                    int col = wn * 64 + tn * 8 + gc;
                    float v0 = acc1[tm][tn][sl * 2 + 0], v1 = acc1[tm][tn][sl * 2 + 1];
                    float n0 = (v0 - mu) * inv * g2[col] + b2[col];
                    float n1 = (v1 - mu) * inv * g2[col + 1] + b2[col + 1];
                    // xn2 -> A tiles (swizzled layout)
                    int ch = (col & 63) >> 3;
                    *(uint32_t*)(smem + (col >> 6) * 8192 + lrow * 128
                                 + ((ch ^ (lrow & 7)) * 16) + (col & 7) * 2) = pack_bf2(n0, n1);
                }
            }
        }
        // no extra sync: step 2's head sync orders xn2 writes before reads
    }

    // ---- MLP: interleaved fc1(nt) -> h tile -> fc2 partial ----
    const float is2 = 0.70710678118654752f;
    for (int nt = 0; nt < 4; nt++) {
        float acc1[2][8][4];
        #pragma unroll
        for (int i = 0; i < 2; i++)
            #pragma unroll
            for (int j = 0; j < 8; j++)
                #pragma unroll
                for (int q = 0; q < 4; q++) acc1[i][j][q] = 0.0f;
        #pragma unroll
        for (int kt = 0; kt < 2; kt++) {
            int s = 2 + nt * 4 + kt;
            stepHead(s);
            mma_tile_sw(smem + kt * 8192, smem + MG_W0 + (s % 3) * 16384, wm, wn, lane, acc1);
        }
        // h epilogue: gelu(acc1 + b1) -> h tiles (swizzled)
        #pragma unroll
        for (int tm = 0; tm < 2; tm++) {
            #pragma unroll
            for (int tn = 0; tn < 8; tn++) {
                int col = wn * 64 + tn * 8 + gc;          // local 0..127
                int colg = nt * 128 + col;
                float bs0 = b1[colg], bs1 = b1[colg + 1];
                int lrow0 = wm * 32 + tm * 16 + gr;
                float v0 = acc1[tm][tn][0] + bs0, v1 = acc1[tm][tn][1] + bs1;
                float v2 = acc1[tm][tn][2] + bs0, v3 = acc1[tm][tn][3] + bs1;
                v0 = 0.5f * v0 * (1.0f + erff(v0 * is2));
                v1 = 0.5f * v1 * (1.0f + erff(v1 * is2));
                v2 = 0.5f * v2 * (1.0f + erff(v2 * is2));
                v3 = 0.5f * v3 * (1.0f + erff(v3 * is2));
                int ch = (col & 63) >> 3;
                int base = MG_H0 + (col >> 6) * 8192 + (col & 7) * 2;
                *(uint32_t*)(smem + base + lrow0 * 128 + ((ch ^ (lrow0 & 7)) * 16)) = pack_bf2(v0, v1);
                int lr1 = lrow0 + 8;
                *(uint32_t*)(smem + base + lr1 * 128 + ((ch ^ (lr1 & 7)) * 16)) = pack_bf2(v2, v3);
            }
        }
        // fc2 partial: next steps' head syncs order h writes before reads
        #pragma unroll
        for (int q = 0; q < 2; q++) {
            int s = 4 + nt * 4 + q;
            stepHead(s);
            mma_tile_sw(smem + MG_H0 + q * 8192, smem + MG_W0 + (s % 3) * 16384, wm, wn, lane, acc2);
        }
    }

    // ---- final epilogue: out = acc2 + b2b + x1 (all thread-local x1 slots) ----
    #pragma unroll
    for (int tm = 0; tm < 2; tm++) {
        #pragma unroll
        for (int tn = 0; tn < 8; tn++) {
            int col = wn * 64 + tn * 8 + gc;
            float bs0 = b2b[col], bs1 = b2b[col + 1];
            int lrow0 = wm * 32 + tm * 16 + gr;
            size_t grow0 = (size_t)(bR * 64 + lrow0);
            float2 x0 = *(const float2*)x1addr(smem, lrow0, col);
            float2 x1v = *(const float2*)x1addr(smem, lrow0 + 8, col);
            float v0 = acc2[tm][tn][0] + bs0, v1 = acc2[tm][tn][1] + bs1;
            float v2 = acc2[tm][tn][2] + bs0, v3 = acc2[tm][tn][3] + bs1;
            *(float2*)(out + grow0 * CDIM + col)       = make_float2(v0 + x0.x, v1 + x0.y);
            *(float2*)(out + (grow0 + 8) * CDIM + col) = make_float2(v2 + x1v.x, v3 + x1v.y);
        }
    }
}

// ---------------- tensor-core window attention, split-precision P@V ----------------
__global__ void __launch_bounds__(256)
attn_kernel(const __nv_bfloat16* __restrict__ qkv, const __nv_bfloat16* __restrict__ vlo,
            const float* __restrict__ rpb, __nv_bfloat16* __restrict__ outw) {
    extern __shared__ unsigned char sm[];
    const int widx = blockIdx.x;
    const int tid = threadIdx.x;

    #pragma unroll
    for (int it = 0; it < 12; it++) {
        int idx = it * 256 + tid;
        int c4 = idx & 3, row = (idx >> 2) & 63, h = (idx >> 8) & 3, t = idx >> 10;
        uint4 v = make_uint4(0, 0, 0, 0);
        if (row < 49)
            v = *(const uint4*)(qkv + (size_t)widx * 18816 + row * 384 + t * 128 + h * 32 + c4 * 8);
        *(uint4*)(sm + h * 15360 + t * 5120 + row * 80 + c4 * 16) = v;
    }
    #pragma unroll
    for (int it = 0; it < 4; it++) {
        int idx = it * 256 + tid;
        int c4 = idx & 3, row = (idx >> 2) & 63, h = idx >> 8;
        uint4 v = make_uint4(0, 0, 0, 0);
        if (row < 49)
            v = *(const uint4*)(vlo + ((size_t)widx * 49 + row) * 128 + h * 32 + c4 * 8);
        *(uint4*)(sm + 61440 + h * 5120 + row * 80 + c4 * 16) = v;
    }
    float* rp = (float*)(sm + 81920);
    for (int p = tid; p < 676; p += 256) rp[p] = rpb[(p % 169) * 4 + (p / 169)];
    int* regs = (int*)(sm + 84624);
    signed char* i2t = (signed char*)(sm + 84880);
    signed char* j2t = (signed char*)(sm + 84944);
    if (tid < 64) { i2t[tid] = tid / 7; j2t[tid] = tid % 7; }
    if (tid < 49) {
        int wi = widx & 63;
        int wh = wi >> 3, ww = wi & 7;
        int i = tid / 7, j = tid - i * 7;
        int grr = wh * 7 + i, gcc = ww * 7 + j;
        int rr = grr < 49 ? 0 : (grr < 53 ? 1 : 2);
        int rc = gcc < 49 ? 0 : (gcc < 53 ? 1 : 2);
        regs[tid] = rr * 3 + rc;
    }
    __syncthreads();

    const int warp = tid >> 5, lane = tid & 31;
    const int h = warp >> 1, half = warp & 1;
    const int mat = lane >> 3, l7 = lane & 7, gr = lane >> 2, gc = (lane & 3) * 2;
    const unsigned char* Q = sm + h * 15360;
    const unsigned char* Kp = Q + 5120;
    const unsigned char* Vp = Q + 10240;
    const unsigned char* Vl = sm + 61440 + h * 5120;

    float sacc[2][8][4];
    #pragma unroll
    for (int i = 0; i < 2; i++)
        #pragma unroll
        for (int j = 0; j < 8; j++)
            #pragma unroll
            for (int q = 0; q < 4; q++) sacc[i][j][q] = 0.0f;

    #pragma unroll
    for (int kc = 0; kc < 2; kc++) {
        uint32_t a[2][4];
        #pragma unroll
        for (int tm = 0; tm < 2; tm++)
            ldsm4(a[tm][0], a[tm][1], a[tm][2], a[tm][3],
                  (uint32_t)__cvta_generic_to_shared(Q + (half * 32 + tm * 16 + (mat & 1) * 8 + l7) * 80 + kc * 32 + (mat >> 1) * 16));
        uint32_t b[4][4];
        #pragma unroll
        for (int tn2 = 0; tn2 < 4; tn2++)
            ldsm4(b[tn2][0], b[tn2][1], b[tn2][2], b[tn2][3],
                  (uint32_t)__cvta_generic_to_shared(Kp + (tn2 * 16 + (mat >> 1) * 8 + l7) * 80 + kc * 32 + (mat & 1) * 16));
        #pragma unroll
        for (int tm = 0; tm < 2; tm++)
            #pragma unroll
            for (int tn = 0; tn < 8; tn++)
                mma16816(sacc[tm][tn], a[tm], b[tn >> 1][(tn & 1) * 2], b[tn >> 1][(tn & 1) * 2 + 1]);
    }

    const float scale = 0.17677669529663687f;
    uint32_t pa[2][4][4], pl[2][4][4];
    #pragma unroll
    for (int tm = 0; tm < 2; tm++) {
        #pragma unroll
        for (int slot = 0; slot < 2; slot++) {
            int n = half * 32 + tm * 16 + gr + slot * 8;
            bool valid = n < 49;
            int i1 = 0, j1 = 0, regn = 0;
            if (valid) { i1 = i2t[n]; j1 = j2t[n]; regn = regs[n]; }
            float vv[16];
            float mx = -1e30f;
            #pragma unroll
            for (int tn = 0; tn < 8; tn++) {
                #pragma unroll
                for (int e = 0; e < 2; e++) {
                    int m = tn * 8 + gc + e;
                    float v = -1e30f;
                    if (valid && m < 49) {
                        v = sacc[tm][tn][slot * 2 + e] * scale
                          + rp[h * 169 + (i1 - i2t[m] + 6) * 13 + (j1 - j2t[m] + 6)];
                        if (regs[m] != regn) v -= 100.0f;
                    }
                    vv[tn * 2 + e] = v;
                    mx = fmaxf(mx, v);
                }
            }
            mx = fmaxf(mx, __shfl_xor_sync(0xFFFFFFFFu, mx, 1));
            mx = fmaxf(mx, __shfl_xor_sync(0xFFFFFFFFu, mx, 2));
            float sum = 0.0f;
            #pragma unroll
            for (int i = 0; i < 16; i++) { vv[i] = __expf(vv[i] - mx); sum += vv[i]; }
            sum += __shfl_xor_sync(0xFFFFFFFFu, sum, 1);
            sum += __shfl_xor_sync(0xFFFFFFFFu, sum, 2);
            float inv = valid ? __frcp_rn(sum) : 0.0f;
            #pragma unroll
            for (int tn = 0; tn < 8; tn++) {
                float p0 = vv[tn * 2] * inv, p1 = vv[tn * 2 + 1] * inv;
                uint32_t u = pack_bf2(p0, p1);
                pa[tm][tn >> 1][(tn & 1) * 2 + slot] = u;
                float h0 = __uint_as_float(u << 16), h1 = __uint_as_float(u & 0xFFFF0000u);
                pl[tm][tn >> 1][(tn & 1) * 2 + slot] = pack_bf2(p0 - h0, p1 - h1);
            }
        }
    }

    float oacc[2][4][4];
    #pragma unroll
    for (int i = 0; i < 2; i++)
        #pragma unroll
        for (int j = 0; j < 4; j++)
            #pragma unroll
            for (int q = 0; q < 4; q++) oacc[i][j][q] = 0.0f;

    #pragma unroll
    for (int kk = 0; kk < 4; kk++) {
        uint32_t bh[2][4], bl[2][4];
        #pragma unroll
        for (int dd = 0; dd < 2; dd++) {
            ldsm4t(bh[dd][0], bh[dd][1], bh[dd][2], bh[dd][3],
                   (uint32_t)__cvta_generic_to_shared(Vp + (kk * 16 + (mat & 1) * 8 + l7) * 80 + dd * 32 + (mat >> 1) * 16));
            ldsm4t(bl[dd][0], bl[dd][1], bl[dd][2], bl[dd][3],
                   (uint32_t)__cvta_generic_to_shared(Vl + (kk * 16 + (mat & 1) * 8 + l7) * 80 + dd * 32 + (mat >> 1) * 16));
        }
        #pragma unroll
        for (int tm = 0; tm < 2; tm++) {
            #pragma unroll
            for (int dd = 0; dd < 2; dd++) {
                mma16816(oacc[tm][dd * 2 + 0], pa[tm][kk], bh[dd][0], bh[dd][1]);
                mma16816(oacc[tm][dd * 2 + 0], pl[tm][kk], bh[dd][0], bh[dd][1]);
                mma16816(oacc[tm][dd * 2 + 0], pa[tm][kk], bl[dd][0], bl[dd][1]);
                mma16816(oacc[tm][dd * 2 + 1], pa[tm][kk], bh[dd][2], bh[dd][3]);
                mma16816(oacc[tm][dd * 2 + 1], pl[tm][kk], bh[dd][2], bh[dd][3]);
                mma16816(oacc[tm][dd * 2 + 1], pa[tm][kk], bl[dd][2], bl[dd][3]);
            }
        }
    }

    #pragma unroll
    for (int tm = 0; tm < 2; tm++) {
        int n0 = half * 32 + tm * 16 + gr;
        #pragma unroll
        for (int dt = 0; dt < 4; dt++) {
            int col = h * 32 + dt * 8 + gc;
            if (n0 < 49)
                *(__nv_bfloat162*)(outw + ((size_t)widx * 49 + n0) * 128 + col) =
                    __floats2bfloat162_rn(oacc[tm][dt][0], oacc[tm][dt][1]);
            if (n0 + 8 < 49)
                *(__nv_bfloat162*)(outw + ((size_t)widx * 49 + n0 + 8) * 128 + col) =
                    __floats2bfloat162_rn(oacc[tm][dt][2], oacc[tm][dt][3]);
        }
    }
}

// ---------------- launch ----------------
#define ATTN_SMEM 85008

extern "C" void kernel_launch(void* const* d_in, const int* in_sizes, int n_in,
                              void* d_out, int out_size) {
    const float* x      = (const float*)d_in[0];
    const float* n1g    = (const float*)d_in[1];
    const float* n1b    = (const float*)d_in[2];
    const float* qkv_w  = (const float*)d_in[3];
    const float* qkv_b  = (const float*)d_in[4];
    const float* proj_w = (const float*)d_in[5];
    const float* proj_b = (const float*)d_in[6];
    const float* rpb    = (const float*)d_in[7];
    const float* n2g    = (const float*)d_in[8];
    const float* n2b    = (const float*)d_in[9];
    const float* fc1_w  = (const float*)d_in[10];
    const float* fc1_b  = (const float*)d_in[11];
    const float* fc2_w  = (const float*)d_in[12];
    const float* fc2_b  = (const float*)d_in[13];
    float* out = (float*)d_out;

    __nv_bfloat16 *qkvb, *vlo, *attnb, *wq, *wp, *w1, *w2;
    cudaGetSymbolAddress((void**)&qkvb, g_qkv);
    cudaGetSymbolAddress((void**)&vlo,  g_vlo);
    cudaGetSymbolAddress((void**)&attnb,g_attn);
    cudaGetSymbolAddress((void**)&wq,   g_wq);
    cudaGetSymbolAddress((void**)&wp,   g_wp);
    cudaGetSymbolAddress((void**)&w1,   g_w1);
    cudaGetSymbolAddress((void**)&w2,   g_w2);

    cudaFuncSetAttribute((const void*)qkv_fused, cudaFuncAttributeMaxDynamicSharedMemorySize, QK_SMEM);
    cudaFuncSetAttribute((const void*)attn_kernel, cudaFuncAttributeMaxDynamicSharedMemorySize, ATTN_SMEM);
    cudaFuncSetAttribute((const void*)mlp_fused, cudaFuncAttributeMaxDynamicSharedMemorySize, MLP_SMEM);

    // 1. all weight conversions in one launch
    f2bf_all<<<192, 256>>>(qkv_w, proj_w, fc1_w, fc2_w, wq, wp, w1, w2);
    // 2. fused LN1 + shift/window gather + QKV GEMM (3-buf ring, 1 sync/step)
    qkv_fused<<<MROWS / 128, 256, QK_SMEM>>>(x, n1g, n1b, wq, qkv_b, qkvb, vlo);
    // 3. tensor-core window attention (split P/V) -> bf16
    attn_kernel<<<NWB, 256, ATTN_SMEM>>>(qkvb, vlo, rpb, attnb);
    // 4. fused proj + resid + LN2 + fc1 + GELU + fc2 + resid -> out
    //    (3-buf ring, 1 sync/step, 112KB smem exactly -> 2 CTAs/SM)
    mlp_fused<<<MROWS / 64, 128, MLP_SMEM>>>(attnb, x, wp, proj_b, n2g, n2b,
                                             w1, fc1_b, w2, fc2_b, out);
}